// round 5
// baseline (speedup 1.0000x reference)
#include <cuda_runtime.h>
#include <math.h>

#define B_ 4
#define LQ 2048
#define LK 2048
#define DM 512
#define NH 2
#define DH 64
#define HD 128   /* NH*DH */

// ---- scratch (static device globals; no allocation) ----
__device__ float g_q[(size_t)B_ * LQ * HD];
__device__ float g_k[(size_t)B_ * LK * HD];
__device__ float g_v[(size_t)B_ * LK * HD];
__device__ float g_ho[(size_t)B_ * LQ * HD];

// =====================================================================
// Generic NN GEMM: C = A(MxK, lda) @ B(KxN, ldb) (+bias), 64x64 tile,
// 256 threads, 4x4 per-thread micro-tile. Batched via blockIdx.z with
// (hi,lo) offsets:  ptr += (z>>1)*offHi + (z&1)*offLo.
// =====================================================================
__global__ __launch_bounds__(256) void gemm_nn(
    const float* __restrict__ A, int lda, long offAhi, long offAlo,
    const float* __restrict__ Bm, int ldb, long offBhi, long offBlo,
    const float* __restrict__ bias,
    float* __restrict__ C, int ldc, long offChi, long offClo,
    int K)
{
    int z = blockIdx.z;
    A  += (long)(z >> 1) * offAhi + (long)(z & 1) * offAlo;
    Bm += (long)(z >> 1) * offBhi + (long)(z & 1) * offBlo;
    C  += (long)(z >> 1) * offChi + (long)(z & 1) * offClo;

    __shared__ float As[64][25];   // [m][kk], stride 25 => conflict-light scalar reads
    __shared__ float Bs[16][80];   // [kk][n], stride 80 floats (320B) => aligned float4

    int tid = threadIdx.x;
    int tx = tid & 15, ty = tid >> 4;
    int row0 = blockIdx.y * 64, col0 = blockIdx.x * 64;

    int lm  = tid >> 2, lk4 = (tid & 3) << 2;   // As loader: 64 rows x 4-float chunk
    int bkk = tid >> 4, bn4 = (tid & 15) << 2;  // Bs loader: 16 k x 4-float chunk

    float acc[4][4] = {};

    for (int k0 = 0; k0 < K; k0 += 16) {
        float4 av = *reinterpret_cast<const float4*>(&A[(size_t)(row0 + lm) * lda + k0 + lk4]);
        float4 bv = *reinterpret_cast<const float4*>(&Bm[(size_t)(k0 + bkk) * ldb + col0 + bn4]);
        As[lm][lk4 + 0] = av.x;
        As[lm][lk4 + 1] = av.y;
        As[lm][lk4 + 2] = av.z;
        As[lm][lk4 + 3] = av.w;
        *reinterpret_cast<float4*>(&Bs[bkk][bn4]) = bv;
        __syncthreads();
        #pragma unroll
        for (int kk = 0; kk < 16; ++kk) {
            float a0 = As[ty * 4 + 0][kk];
            float a1 = As[ty * 4 + 1][kk];
            float a2 = As[ty * 4 + 2][kk];
            float a3 = As[ty * 4 + 3][kk];
            float4 b4 = *reinterpret_cast<const float4*>(&Bs[kk][tx * 4]);
            acc[0][0] += a0 * b4.x; acc[0][1] += a0 * b4.y; acc[0][2] += a0 * b4.z; acc[0][3] += a0 * b4.w;
            acc[1][0] += a1 * b4.x; acc[1][1] += a1 * b4.y; acc[1][2] += a1 * b4.z; acc[1][3] += a1 * b4.w;
            acc[2][0] += a2 * b4.x; acc[2][1] += a2 * b4.y; acc[2][2] += a2 * b4.z; acc[2][3] += a2 * b4.w;
            acc[3][0] += a3 * b4.x; acc[3][1] += a3 * b4.y; acc[3][2] += a3 * b4.z; acc[3][3] += a3 * b4.w;
        }
        __syncthreads();
    }

    #pragma unroll
    for (int i = 0; i < 4; ++i) {
        int r = row0 + ty * 4 + i;
        #pragma unroll
        for (int j = 0; j < 4; ++j) {
            int c = col0 + tx * 4 + j;
            float v = acc[i][j];
            if (bias) v += bias[c];
            C[(size_t)r * ldc + c] = v;
        }
    }
}

// =====================================================================
// Scores: S[b,h,q,k] = tanh( (q . k)/8 ) * 10 ;  masked cols -> -10
// A = q rows (2048 x 64, ld HD), B = k rows (2048 x 64, ld HD), NT product.
// =====================================================================
__global__ __launch_bounds__(256) void gemm_nt_scores(
    const float* __restrict__ qp, const float* __restrict__ kp,
    const int* __restrict__ mask, float* __restrict__ S)
{
    int z = blockIdx.z, b = z >> 1, h = z & 1;
    const float* A  = qp + (size_t)b * LQ * HD + h * DH;
    const float* Bm = kp + (size_t)b * LK * HD + h * DH;
    float* Sout = S + (size_t)z * LQ * LK;

    __shared__ float As[64][25];
    __shared__ float Bs[64][25];

    int tid = threadIdx.x, tx = tid & 15, ty = tid >> 4;
    int row0 = blockIdx.y * 64, col0 = blockIdx.x * 64;
    int lm = tid >> 2, lk4 = (tid & 3) << 2;

    float acc[4][4] = {};

    #pragma unroll
    for (int k0 = 0; k0 < DH; k0 += 16) {
        float4 av = *reinterpret_cast<const float4*>(&A[(size_t)(row0 + lm) * HD + k0 + lk4]);
        float4 bv = *reinterpret_cast<const float4*>(&Bm[(size_t)(col0 + lm) * HD + k0 + lk4]);
        As[lm][lk4 + 0] = av.x; As[lm][lk4 + 1] = av.y; As[lm][lk4 + 2] = av.z; As[lm][lk4 + 3] = av.w;
        Bs[lm][lk4 + 0] = bv.x; Bs[lm][lk4 + 1] = bv.y; Bs[lm][lk4 + 2] = bv.z; Bs[lm][lk4 + 3] = bv.w;
        __syncthreads();
        #pragma unroll
        for (int kk = 0; kk < 16; ++kk) {
            float a[4], bb[4];
            #pragma unroll
            for (int i = 0; i < 4; ++i) a[i] = As[ty * 4 + i][kk];
            #pragma unroll
            for (int j = 0; j < 4; ++j) bb[j] = Bs[tx * 4 + j][kk];
            #pragma unroll
            for (int i = 0; i < 4; ++i)
                #pragma unroll
                for (int j = 0; j < 4; ++j)
                    acc[i][j] += a[i] * bb[j];
        }
        __syncthreads();
    }

    int mv[4];
    #pragma unroll
    for (int j = 0; j < 4; ++j) mv[j] = mask[b * LK + col0 + tx * 4 + j];

    #pragma unroll
    for (int i = 0; i < 4; ++i) {
        int r = row0 + ty * 4 + i;
        #pragma unroll
        for (int j = 0; j < 4; ++j) {
            float s = tanhf(acc[i][j] * 0.125f) * 10.0f;
            if (mv[j]) s = -10.0f;
            Sout[(size_t)r * LK + col0 + tx * 4 + j] = s;
        }
    }
}

// =====================================================================
// Log-softmax fixup: one block per (b,h,q) row; attn = s - logsumexp(s)
// =====================================================================
__global__ __launch_bounds__(256) void lse_fixup(float* __restrict__ attn)
{
    __shared__ float red[8];
    float* p = attn + (size_t)blockIdx.x * LK;
    int tid = threadIdx.x;

    float vals[8];
    float m = -1e30f;
    #pragma unroll
    for (int j = 0; j < 8; ++j) {
        vals[j] = p[tid + j * 256];
        m = fmaxf(m, vals[j]);
    }
    #pragma unroll
    for (int o = 16; o; o >>= 1) m = fmaxf(m, __shfl_xor_sync(0xffffffffu, m, o));
    if ((tid & 31) == 0) red[tid >> 5] = m;
    __syncthreads();
    float bm = red[0];
    #pragma unroll
    for (int w = 1; w < 8; ++w) bm = fmaxf(bm, red[w]);
    __syncthreads();

    float s = 0.0f;
    #pragma unroll
    for (int j = 0; j < 8; ++j) s += __expf(vals[j] - bm);
    #pragma unroll
    for (int o = 16; o; o >>= 1) s += __shfl_xor_sync(0xffffffffu, s, o);
    if ((tid & 31) == 0) red[tid >> 5] = s;
    __syncthreads();
    float ts = 0.0f;
    #pragma unroll
    for (int w = 0; w < 8; ++w) ts += red[w];

    float lse = bm + logf(ts);
    #pragma unroll
    for (int j = 0; j < 8; ++j) p[tid + j * 256] = vals[j] - lse;
}

// =====================================================================
extern "C" void kernel_launch(void* const* d_in, const int* in_sizes, int n_in,
                              void* d_out, int out_size)
{
    const float* Q    = (const float*)d_in[0];
    const float* K    = (const float*)d_in[1];
    const float* V    = (const float*)d_in[2];
    const int*   mask = (const int*)  d_in[3];
    const float* Wq   = (const float*)d_in[4];
    const float* bq   = (const float*)d_in[5];
    const float* Wk   = (const float*)d_in[6];
    const float* bk   = (const float*)d_in[7];
    const float* Wv   = (const float*)d_in[8];
    const float* bv   = (const float*)d_in[9];
    const float* Wo   = (const float*)d_in[10];
    const float* bo   = (const float*)d_in[11];

    float* out  = (float*)d_out;
    float* attn = out + (size_t)B_ * LQ * DM;   // attn region follows `out`

    float *gq, *gk, *gv, *gho;
    cudaGetSymbolAddress((void**)&gq,  g_q);
    cudaGetSymbolAddress((void**)&gk,  g_k);
    cudaGetSymbolAddress((void**)&gv,  g_v);
    cudaGetSymbolAddress((void**)&gho, g_ho);

    dim3 blk(256);

    // 1) projections: [8192,512] @ [512,128] + bias
    dim3 gproj(HD / 64, (B_ * LQ) / 64, 1);
    gemm_nn<<<gproj, blk>>>(Q, DM, 0, 0, Wq, HD, 0, 0, bq, gq, HD, 0, 0, DM);
    gemm_nn<<<gproj, blk>>>(K, DM, 0, 0, Wk, HD, 0, 0, bk, gk, HD, 0, 0, DM);
    gemm_nn<<<gproj, blk>>>(V, DM, 0, 0, Wv, HD, 0, 0, bv, gv, HD, 0, 0, DM);

    // 2) scores (writes raw clipped/masked s into attn region)
    gemm_nt_scores<<<dim3(LK / 64, LQ / 64, B_ * NH), blk>>>(gq, gk, mask, attn);

    // 3) log-softmax fixup in place
    lse_fixup<<<B_ * NH * LQ, 256>>>(attn);

    // 4) head_out = attn @ v   (batched over 8 (b,h); N = 64)
    gemm_nn<<<dim3(1, LQ / 64, B_ * NH), blk>>>(
        attn, LK, 2L * LQ * LK, (long)LQ * LK,
        gv,   HD, (long)LK * HD, (long)DH,
        (const float*)0,
        gho,  HD, (long)LQ * HD, (long)DH,
        LK);

    // 5) out = head_out @ Wo + bo : [8192,128] @ [128,512]
    gemm_nn<<<dim3(DM / 64, (B_ * LQ) / 64, 1), blk>>>(
        gho, HD, 0, 0, Wo, DM, 0, 0, bo, out, DM, 0, 0, HD);
}

// round 10
// speedup vs baseline: 2.1106x; 2.1106x over previous
#include <cuda_runtime.h>
#include <cuda_bf16.h>
#include <math.h>
#include <stdint.h>

#define B_ 4
#define LQ 2048
#define LK 2048
#define DM 512
#define NH 2
#define DH 64
#define HD 128   /* NH*DH */

// ---------------- scratch (device globals; no allocation) ----------------
__device__ __nv_bfloat16 g_qh[(size_t)B_*NH*LQ*DH];
__device__ __nv_bfloat16 g_ql[(size_t)B_*NH*LQ*DH];
__device__ __nv_bfloat16 g_kh[(size_t)B_*NH*LK*DH];
__device__ __nv_bfloat16 g_kl[(size_t)B_*NH*LK*DH];
__device__ __nv_bfloat16 g_vth[(size_t)B_*NH*DH*LK];   // v transposed: [z][d][k]
__device__ __nv_bfloat16 g_vtl[(size_t)B_*NH*DH*LK];
__device__ float g_part[(size_t)B_*NH*LQ*32];          // per-row per-64col exp sums
__device__ float g_lse [(size_t)B_*NH*LQ];
__device__ float g_ho  [(size_t)B_*LQ*HD];             // [b*LQ+q][h*64+d]

// ---------------- helpers ----------------
__device__ __forceinline__ uint32_t smem_u32(const void* p) {
    uint32_t a;
    asm("{ .reg .u64 t; cvta.to.shared.u64 t, %1; cvt.u32.u64 %0, t; }" : "=r"(a) : "l"(p));
    return a;
}
__device__ __forceinline__ uint32_t pack2(__nv_bfloat16 a, __nv_bfloat16 b) {
    __nv_bfloat162 t; t.x = a; t.y = b;
    return *reinterpret_cast<uint32_t*>(&t);
}

#define LDSM_X4(R0,R1,R2,R3,ADDR) \
    asm volatile("ldmatrix.sync.aligned.m8n8.x4.shared.b16 {%0,%1,%2,%3}, [%4];" \
        : "=r"(R0),"=r"(R1),"=r"(R2),"=r"(R3) : "r"(ADDR))

#define MMA_BF16(C,A0,A1,A2,A3,B0,B1) \
    asm volatile("mma.sync.aligned.m16n8k16.row.col.f32.bf16.bf16.f32 " \
        "{%0,%1,%2,%3}, {%4,%5,%6,%7}, {%8,%9}, {%0,%1,%2,%3};" \
        : "+f"((C)[0]),"+f"((C)[1]),"+f"((C)[2]),"+f"((C)[3]) \
        : "r"(A0),"r"(A1),"r"(A2),"r"(A3),"r"(B0),"r"(B1))

// tanh(x)*10, NaN-safe (clamp keeps exp finite); ~1e-6 abs error
__device__ __forceinline__ float tanh10(float x) {
    x = fminf(fmaxf(x, -15.0f), 15.0f);
    float e = __expf(2.0f * x);
    return 10.0f * __fdividef(e - 1.0f, e + 1.0f);
}

// =====================================================================
// Projections: X[8192,512] @ W[512,128] + bias -> bf16 hi/lo.
// vmode 0: q/k layout [z][row][64].  vmode 1: v transposed [z][d][k].
// =====================================================================
__global__ __launch_bounds__(256) void proj_kernel(
    const float* __restrict__ A, const float* __restrict__ W,
    const float* __restrict__ bias,
    __nv_bfloat16* __restrict__ oh, __nv_bfloat16* __restrict__ ol, int vmode)
{
    __shared__ float As[64][25];
    __shared__ float Bs[16][80];
    __shared__ float ts[64][65];

    int tid = threadIdx.x, tx = tid & 15, ty = tid >> 4;
    int row0 = blockIdx.y * 64;
    int h = blockIdx.x;
    int col0 = h * 64;
    int lm = tid >> 2, lk4 = (tid & 3) << 2;
    int bkk = tid >> 4, bn4 = (tid & 15) << 2;

    float acc[4][4] = {};
    for (int k0 = 0; k0 < DM; k0 += 16) {
        float4 av = *reinterpret_cast<const float4*>(&A[(size_t)(row0 + lm) * DM + k0 + lk4]);
        float4 bv = *reinterpret_cast<const float4*>(&W[(size_t)(k0 + bkk) * HD + col0 + bn4]);
        As[lm][lk4 + 0] = av.x; As[lm][lk4 + 1] = av.y;
        As[lm][lk4 + 2] = av.z; As[lm][lk4 + 3] = av.w;
        *reinterpret_cast<float4*>(&Bs[bkk][bn4]) = bv;
        __syncthreads();
        #pragma unroll
        for (int kk = 0; kk < 16; ++kk) {
            float a0 = As[ty * 4 + 0][kk], a1 = As[ty * 4 + 1][kk];
            float a2 = As[ty * 4 + 2][kk], a3 = As[ty * 4 + 3][kk];
            float4 b4 = *reinterpret_cast<const float4*>(&Bs[kk][tx * 4]);
            acc[0][0] += a0 * b4.x; acc[0][1] += a0 * b4.y; acc[0][2] += a0 * b4.z; acc[0][3] += a0 * b4.w;
            acc[1][0] += a1 * b4.x; acc[1][1] += a1 * b4.y; acc[1][2] += a1 * b4.z; acc[1][3] += a1 * b4.w;
            acc[2][0] += a2 * b4.x; acc[2][1] += a2 * b4.y; acc[2][2] += a2 * b4.z; acc[2][3] += a2 * b4.w;
            acc[3][0] += a3 * b4.x; acc[3][1] += a3 * b4.y; acc[3][2] += a3 * b4.z; acc[3][3] += a3 * b4.w;
        }
        __syncthreads();
    }

    #pragma unroll
    for (int i = 0; i < 4; ++i)
        #pragma unroll
        for (int j = 0; j < 4; ++j)
            acc[i][j] += bias[col0 + tx * 4 + j];

    if (vmode == 0) {
        #pragma unroll
        for (int i = 0; i < 4; ++i) {
            int rg = row0 + ty * 4 + i;
            int b = rg >> 11, r = rg & 2047;
            size_t off = ((size_t)(b * NH + h) * LQ + r) * 64 + tx * 4;
            __nv_bfloat16 h0 = __float2bfloat16(acc[i][0]);
            __nv_bfloat16 h1 = __float2bfloat16(acc[i][1]);
            __nv_bfloat16 h2 = __float2bfloat16(acc[i][2]);
            __nv_bfloat16 h3 = __float2bfloat16(acc[i][3]);
            uint2 hv = make_uint2(pack2(h0, h1), pack2(h2, h3));
            uint2 lv = make_uint2(
                pack2(__float2bfloat16(acc[i][0] - __bfloat162float(h0)),
                      __float2bfloat16(acc[i][1] - __bfloat162float(h1))),
                pack2(__float2bfloat16(acc[i][2] - __bfloat162float(h2)),
                      __float2bfloat16(acc[i][3] - __bfloat162float(h3))));
            *reinterpret_cast<uint2*>(&oh[off]) = hv;
            *reinterpret_cast<uint2*>(&ol[off]) = lv;
        }
    } else {
        __syncthreads();
        #pragma unroll
        for (int i = 0; i < 4; ++i)
            #pragma unroll
            for (int j = 0; j < 4; ++j)
                ts[ty * 4 + i][tx * 4 + j] = acc[i][j];
        __syncthreads();

        int d = tid >> 2, seg = tid & 3;
        int b = row0 >> 11;
        int kbase = (row0 & 2047) + seg * 16;
        size_t off = ((size_t)(b * NH + h) * 64 + d) * (size_t)LK + kbase;
        uint32_t hw[8], lw[8];
        #pragma unroll
        for (int p = 0; p < 8; ++p) {
            float v0 = ts[seg * 16 + p * 2 + 0][d];
            float v1 = ts[seg * 16 + p * 2 + 1][d];
            __nv_bfloat16 h0 = __float2bfloat16(v0);
            __nv_bfloat16 h1 = __float2bfloat16(v1);
            hw[p] = pack2(h0, h1);
            lw[p] = pack2(__float2bfloat16(v0 - __bfloat162float(h0)),
                          __float2bfloat16(v1 - __bfloat162float(h1)));
        }
        *reinterpret_cast<uint4*>(&oh[off])     = make_uint4(hw[0], hw[1], hw[2], hw[3]);
        *reinterpret_cast<uint4*>(&oh[off + 8]) = make_uint4(hw[4], hw[5], hw[6], hw[7]);
        *reinterpret_cast<uint4*>(&ol[off])     = make_uint4(lw[0], lw[1], lw[2], lw[3]);
        *reinterpret_cast<uint4*>(&ol[off + 8]) = make_uint4(lw[4], lw[5], lw[6], lw[7]);
    }
}

// =====================================================================
// QK scores via mma.sync (bf16 hi/lo 3-term): per block one 128x128 tile.
// Writes raw s = tanh(qk/8)*10 (mask->-10) and per-row/64col exp partials.
// smem: mask[128] ints at 0; QH/QL/KH/KL 16KB tiles from 1024.
// =====================================================================
__global__ __launch_bounds__(256) void qk_tc(const int* __restrict__ mask,
                                             float* __restrict__ attn)
{
    extern __shared__ char smem[];
    int tid = threadIdx.x;
    int z = blockIdx.z;
    int q0 = blockIdx.y * 128, k0 = blockIdx.x * 128;
    const uint32_t QH = 1024, QL = QH + 16384, KH = QL + 16384, KL = KH + 16384;

    int* smask = reinterpret_cast<int*>(smem);
    if (tid < 128) smask[tid] = mask[(z >> 1) * LK + k0 + tid];

    {
        size_t qrow = (size_t)z * LQ + q0;
        size_t krow = (size_t)z * LK + k0;
        #pragma unroll
        for (int i = 0; i < 4; ++i) {
            int idx = tid + i * 256;             // 0..1023
            int row = idx >> 3, ch = idx & 7;
            uint32_t so = (uint32_t)row * 128 + (uint32_t)((ch ^ (row & 7)) << 4);
            size_t go = (qrow + row) * 64 + ch * 8;
            size_t gk = (krow + row) * 64 + ch * 8;
            *reinterpret_cast<uint4*>(smem + QH + so) = *reinterpret_cast<const uint4*>(g_qh + go);
            *reinterpret_cast<uint4*>(smem + QL + so) = *reinterpret_cast<const uint4*>(g_ql + go);
            *reinterpret_cast<uint4*>(smem + KH + so) = *reinterpret_cast<const uint4*>(g_kh + gk);
            *reinterpret_cast<uint4*>(smem + KL + so) = *reinterpret_cast<const uint4*>(g_kl + gk);
        }
    }
    __syncthreads();

    uint32_t sb = smem_u32(smem);
    int w = tid >> 5, lane = tid & 31;
    int wy = w & 3, wx = w >> 2;

    float acc[2][8][4] = {};

    uint32_t aoffH[2], aoffL[2];
    int arx[2];
    #pragma unroll
    for (int mt = 0; mt < 2; ++mt) {
        int r = wy * 32 + mt * 16 + (lane & 15);
        arx[mt] = r & 7;
        aoffH[mt] = sb + QH + (uint32_t)r * 128;
        aoffL[mt] = sb + QL + (uint32_t)r * 128;
    }
    int ahib = lane >> 4;
    int nrow0 = wx * 64 + (lane & 7) + ((lane & 16) >> 1);
    int bhib = (lane >> 3) & 1;

    #pragma unroll
    for (int s = 0; s < 4; ++s) {
        uint32_t ah[2][4], al[2][4];
        #pragma unroll
        for (int mt = 0; mt < 2; ++mt) {
            uint32_t c = (uint32_t)(((s * 2 + ahib) ^ arx[mt]) << 4);
            LDSM_X4(ah[mt][0], ah[mt][1], ah[mt][2], ah[mt][3], aoffH[mt] + c);
            LDSM_X4(al[mt][0], al[mt][1], al[mt][2], al[mt][3], aoffL[mt] + c);
        }
        #pragma unroll
        for (int g = 0; g < 4; ++g) {
            int r = nrow0 + g * 16;
            uint32_t bo = (uint32_t)r * 128 + (uint32_t)(((s * 2 + bhib) ^ (r & 7)) << 4);
            uint32_t bh[4], bl[4];
            LDSM_X4(bh[0], bh[1], bh[2], bh[3], sb + KH + bo);
            LDSM_X4(bl[0], bl[1], bl[2], bl[3], sb + KL + bo);
            #pragma unroll
            for (int t2 = 0; t2 < 2; ++t2) {
                int nt = g * 2 + t2;
                #pragma unroll
                for (int mt = 0; mt < 2; ++mt) {
                    MMA_BF16(acc[mt][nt], ah[mt][0], ah[mt][1], ah[mt][2], ah[mt][3],
                             bh[t2 * 2], bh[t2 * 2 + 1]);
                    MMA_BF16(acc[mt][nt], ah[mt][0], ah[mt][1], ah[mt][2], ah[mt][3],
                             bl[t2 * 2], bl[t2 * 2 + 1]);
                    MMA_BF16(acc[mt][nt], al[mt][0], al[mt][1], al[mt][2], al[mt][3],
                             bh[t2 * 2], bh[t2 * 2 + 1]);
                }
            }
        }
    }

    // epilogue: tanh-clip, mask, store raw s, accumulate exp partials
    float rs[2][2] = {};
    #pragma unroll
    for (int mt = 0; mt < 2; ++mt) {
        int r = q0 + wy * 32 + mt * 16 + (lane >> 2);
        float* row0p = attn + (size_t)z * LQ * LK + (size_t)r * LK + k0;
        float* row1p = row0p + (size_t)8 * LK;
        #pragma unroll
        for (int nt = 0; nt < 8; ++nt) {
            int cl = wx * 64 + nt * 8 + (lane & 3) * 2;
            int m0 = smask[cl], m1 = smask[cl + 1];
            float s0 = tanh10(acc[mt][nt][0] * 0.125f);
            float s1 = tanh10(acc[mt][nt][1] * 0.125f);
            float s2 = tanh10(acc[mt][nt][2] * 0.125f);
            float s3 = tanh10(acc[mt][nt][3] * 0.125f);
            if (m0) { s0 = -10.0f; s2 = -10.0f; }
            if (m1) { s1 = -10.0f; s3 = -10.0f; }
            *reinterpret_cast<float2*>(row0p + cl) = make_float2(s0, s1);
            *reinterpret_cast<float2*>(row1p + cl) = make_float2(s2, s3);
            rs[mt][0] += __expf(s0) + __expf(s1);
            rs[mt][1] += __expf(s2) + __expf(s3);
        }
    }
    #pragma unroll
    for (int mt = 0; mt < 2; ++mt)
        #pragma unroll
        for (int hf = 0; hf < 2; ++hf) {
            float v = rs[mt][hf];
            v += __shfl_xor_sync(0xffffffffu, v, 1);
            v += __shfl_xor_sync(0xffffffffu, v, 2);
            rs[mt][hf] = v;
        }
    if ((lane & 3) == 0) {
        int col = blockIdx.x * 2 + wx;
        #pragma unroll
        for (int mt = 0; mt < 2; ++mt)
            #pragma unroll
            for (int hf = 0; hf < 2; ++hf) {
                int r = q0 + wy * 32 + mt * 16 + hf * 8 + (lane >> 2);
                g_part[((size_t)z * LQ + r) * 32 + col] = rs[mt][hf];
            }
    }
}

// =====================================================================
// lse[row] = log( sum of 32 partials )
// =====================================================================
__global__ __launch_bounds__(256) void lse_reduce()
{
    int r = blockIdx.x * 256 + threadIdx.x;
    float s = 0.0f;
    #pragma unroll
    for (int j = 0; j < 32; ++j) s += g_part[(size_t)r * 32 + j];
    g_lse[r] = logf(s);
}

// =====================================================================
// PV via mma.sync: per (z, 64-q tile): loop 32 k-chunks of 64.
// Normalizes attn in-flight (final output), hi/lo bf16 -> smem, MMA vs
// pre-transposed v^T hi/lo.
// =====================================================================
__global__ __launch_bounds__(256) void pv_tc(float* __restrict__ attn)
{
    extern __shared__ char smem[];
    int tid = threadIdx.x;
    int z = blockIdx.y, q0 = blockIdx.x * 64;
    const uint32_t AH = 1024, AL = AH + 8192, VH = AL + 8192, VL = VH + 8192;

    float* s_lse = reinterpret_cast<float*>(smem);
    if (tid < 64) s_lse[tid] = g_lse[(size_t)z * LQ + q0 + tid];
    __syncthreads();

    uint32_t sb = smem_u32(smem);
    int w = tid >> 5, lane = tid & 31;
    int wy = w & 3, wx = w >> 2;
    float acc[4][4] = {};

    int arow = wy * 16 + (lane & 15);
    int arx = arow & 7;
    uint32_t aoffH = sb + AH + (uint32_t)arow * 128;
    uint32_t aoffL = sb + AL + (uint32_t)arow * 128;
    int ahib = lane >> 4;
    int nrow0 = wx * 32 + (lane & 7) + ((lane & 16) >> 1);
    int bhib = (lane >> 3) & 1;

    float* abase = attn + (size_t)z * LQ * LK + (size_t)q0 * LK;

    for (int kc = 0; kc < 32; ++kc) {
        int k0 = kc * 64;

        // stage attn: normalize, write back (final), convert hi/lo to smem
        #pragma unroll
        for (int i = 0; i < 4; ++i) {
            int idx = tid + i * 256;             // 0..1023 float4s
            int row = idx >> 4, pos = idx & 15;
            float* ap = abase + (size_t)row * LK + k0 + pos * 4;
            float4 sv = *reinterpret_cast<float4*>(ap);
            float l = s_lse[row];
            float a0 = sv.x - l, a1 = sv.y - l, a2 = sv.z - l, a3 = sv.w - l;
            *reinterpret_cast<float4*>(ap) = make_float4(a0, a1, a2, a3);
            __nv_bfloat16 h0 = __float2bfloat16(a0), h1 = __float2bfloat16(a1);
            __nv_bfloat16 h2 = __float2bfloat16(a2), h3 = __float2bfloat16(a3);
            uint2 hv = make_uint2(pack2(h0, h1), pack2(h2, h3));
            uint2 lv = make_uint2(
                pack2(__float2bfloat16(a0 - __bfloat162float(h0)),
                      __float2bfloat16(a1 - __bfloat162float(h1))),
                pack2(__float2bfloat16(a2 - __bfloat162float(h2)),
                      __float2bfloat16(a3 - __bfloat162float(h3))));
            int ch = pos >> 1, half = pos & 1;
            uint32_t so = (uint32_t)row * 128 + (uint32_t)((ch ^ (row & 7)) << 4) + half * 8;
            *reinterpret_cast<uint2*>(smem + AH + so) = hv;
            *reinterpret_cast<uint2*>(smem + AL + so) = lv;
        }
        // stage v^T hi/lo: 64 d-rows x 64 k
        #pragma unroll
        for (int i = 0; i < 2; ++i) {
            int idx = tid + i * 256;             // 0..511
            int row = idx >> 3, ch = idx & 7;
            size_t go = ((size_t)z * 64 + row) * (size_t)LK + k0 + ch * 8;
            uint32_t so = (uint32_t)row * 128 + (uint32_t)((ch ^ (row & 7)) << 4);
            *reinterpret_cast<uint4*>(smem + VH + so) = *reinterpret_cast<const uint4*>(g_vth + go);
            *reinterpret_cast<uint4*>(smem + VL + so) = *reinterpret_cast<const uint4*>(g_vtl + go);
        }
        __syncthreads();

        #pragma unroll
        for (int s = 0; s < 4; ++s) {
            uint32_t ah[4], al[4];
            uint32_t ac = (uint32_t)(((s * 2 + ahib) ^ arx) << 4);
            LDSM_X4(ah[0], ah[1], ah[2], ah[3], aoffH + ac);
            LDSM_X4(al[0], al[1], al[2], al[3], aoffL + ac);
            #pragma unroll
            for (int g = 0; g < 2; ++g) {
                int r = nrow0 + g * 16;
                uint32_t bo = (uint32_t)r * 128 + (uint32_t)(((s * 2 + bhib) ^ (r & 7)) << 4);
                uint32_t bh[4], bl[4];
                LDSM_X4(bh[0], bh[1], bh[2], bh[3], sb + VH + bo);
                LDSM_X4(bl[0], bl[1], bl[2], bl[3], sb + VL + bo);
                #pragma unroll
                for (int t2 = 0; t2 < 2; ++t2) {
                    int nt = g * 2 + t2;
                    MMA_BF16(acc[nt], ah[0], ah[1], ah[2], ah[3], bh[t2 * 2], bh[t2 * 2 + 1]);
                    MMA_BF16(acc[nt], ah[0], ah[1], ah[2], ah[3], bl[t2 * 2], bl[t2 * 2 + 1]);
                    MMA_BF16(acc[nt], al[0], al[1], al[2], al[3], bh[t2 * 2], bh[t2 * 2 + 1]);
                }
            }
        }
        __syncthreads();
    }

    // epilogue -> g_ho
    int b = z >> 1, h = z & 1;
    int r0 = q0 + wy * 16 + (lane >> 2);
    float* d0 = g_ho + ((size_t)b * LQ + r0) * HD + h * 64 + wx * 32 + (lane & 3) * 2;
    float* d1 = d0 + (size_t)8 * HD;
    #pragma unroll
    for (int nt = 0; nt < 4; ++nt) {
        *reinterpret_cast<float2*>(d0 + nt * 8) = make_float2(acc[nt][0], acc[nt][1]);
        *reinterpret_cast<float2*>(d1 + nt * 8) = make_float2(acc[nt][2], acc[nt][3]);
    }
}

// =====================================================================
// Output projection (scalar fp32): out = g_ho @ Wo + bo
// =====================================================================
__global__ __launch_bounds__(256) void gemm_nn(
    const float* __restrict__ A, int lda,
    const float* __restrict__ Bm, int ldb,
    const float* __restrict__ bias,
    float* __restrict__ C, int ldc, int K)
{
    __shared__ float As[64][25];
    __shared__ float Bs[16][80];

    int tid = threadIdx.x, tx = tid & 15, ty = tid >> 4;
    int row0 = blockIdx.y * 64, col0 = blockIdx.x * 64;
    int lm = tid >> 2, lk4 = (tid & 3) << 2;
    int bkk = tid >> 4, bn4 = (tid & 15) << 2;

    float acc[4][4] = {};
    for (int k0 = 0; k0 < K; k0 += 16) {
        float4 av = *reinterpret_cast<const float4*>(&A[(size_t)(row0 + lm) * lda + k0 + lk4]);
        float4 bv = *reinterpret_cast<const float4*>(&Bm[(size_t)(k0 + bkk) * ldb + col0 + bn4]);
        As[lm][lk4 + 0] = av.x; As[lm][lk4 + 1] = av.y;
        As[lm][lk4 + 2] = av.z; As[lm][lk4 + 3] = av.w;
        *reinterpret_cast<float4*>(&Bs[bkk][bn4]) = bv;
        __syncthreads();
        #pragma unroll
        for (int kk = 0; kk < 16; ++kk) {
            float a0 = As[ty * 4 + 0][kk], a1 = As[ty * 4 + 1][kk];
            float a2 = As[ty * 4 + 2][kk], a3 = As[ty * 4 + 3][kk];
            float4 b4 = *reinterpret_cast<const float4*>(&Bs[kk][tx * 4]);
            acc[0][0] += a0 * b4.x; acc[0][1] += a0 * b4.y; acc[0][2] += a0 * b4.z; acc[0][3] += a0 * b4.w;
            acc[1][0] += a1 * b4.x; acc[1][1] += a1 * b4.y; acc[1][2] += a1 * b4.z; acc[1][3] += a1 * b4.w;
            acc[2][0] += a2 * b4.x; acc[2][1] += a2 * b4.y; acc[2][2] += a2 * b4.z; acc[2][3] += a2 * b4.w;
            acc[3][0] += a3 * b4.x; acc[3][1] += a3 * b4.y; acc[3][2] += a3 * b4.z; acc[3][3] += a3 * b4.w;
        }
        __syncthreads();
    }
    #pragma unroll
    for (int i = 0; i < 4; ++i) {
        int r = row0 + ty * 4 + i;
        #pragma unroll
        for (int j = 0; j < 4; ++j) {
            int c = col0 + tx * 4 + j;
            C[(size_t)r * ldc + c] = acc[i][j] + bias[c];
        }
    }
}

// =====================================================================
extern "C" void kernel_launch(void* const* d_in, const int* in_sizes, int n_in,
                              void* d_out, int out_size)
{
    const float* Q    = (const float*)d_in[0];
    const float* K    = (const float*)d_in[1];
    const float* V    = (const float*)d_in[2];
    const int*   mask = (const int*)  d_in[3];
    const float* Wq   = (const float*)d_in[4];
    const float* bq   = (const float*)d_in[5];
    const float* Wk   = (const float*)d_in[6];
    const float* bk   = (const float*)d_in[7];
    const float* Wv   = (const float*)d_in[8];
    const float* bv   = (const float*)d_in[9];
    const float* Wo   = (const float*)d_in[10];
    const float* bo   = (const float*)d_in[11];

    float* out  = (float*)d_out;
    float* attn = out + (size_t)B_ * LQ * DM;

    __nv_bfloat16 *qh, *ql, *kh, *kl, *vth, *vtl;
    float *gho;
    cudaGetSymbolAddress((void**)&qh,  g_qh);
    cudaGetSymbolAddress((void**)&ql,  g_ql);
    cudaGetSymbolAddress((void**)&kh,  g_kh);
    cudaGetSymbolAddress((void**)&kl,  g_kl);
    cudaGetSymbolAddress((void**)&vth, g_vth);
    cudaGetSymbolAddress((void**)&vtl, g_vtl);
    cudaGetSymbolAddress((void**)&gho, g_ho);

    cudaFuncSetAttribute(qk_tc, cudaFuncAttributeMaxDynamicSharedMemorySize, 66560);
    cudaFuncSetAttribute(pv_tc, cudaFuncAttributeMaxDynamicSharedMemorySize, 33792);

    dim3 blk(256);
    dim3 gproj(NH, (B_ * LQ) / 64, 1);
    proj_kernel<<<gproj, blk>>>(Q, Wq, bq, qh,  ql,  0);
    proj_kernel<<<gproj, blk>>>(K, Wk, bk, kh,  kl,  0);
    proj_kernel<<<gproj, blk>>>(V, Wv, bv, vth, vtl, 1);

    qk_tc<<<dim3(LK / 128, LQ / 128, B_ * NH), 256, 66560>>>(mask, attn);

    lse_reduce<<<(B_ * NH * LQ) / 256, 256>>>();

    pv_tc<<<dim3(LQ / 64, B_ * NH), 256, 33792>>>(attn);

    gemm_nn<<<dim3(DM / 64, (B_ * LQ) / 64), blk>>>(gho, HD, Wo, DM, bo, out, DM, HD);
}

// round 11
// speedup vs baseline: 2.7121x; 1.2850x over previous
#include <cuda_runtime.h>
#include <cuda_bf16.h>
#include <math.h>
#include <stdint.h>

#define B_ 4
#define LQ 2048
#define LK 2048
#define DM 512
#define NH 2
#define DH 64
#define HD 128   /* NH*DH */

// ---------------- scratch (device globals; no allocation) ----------------
__device__ __nv_bfloat16 g_qh[(size_t)B_*NH*LQ*DH];
__device__ __nv_bfloat16 g_ql[(size_t)B_*NH*LQ*DH];
__device__ __nv_bfloat16 g_kh[(size_t)B_*NH*LK*DH];
__device__ __nv_bfloat16 g_kl[(size_t)B_*NH*LK*DH];
__device__ __nv_bfloat16 g_vth[(size_t)B_*NH*DH*LK];   // v transposed: [z][d][k]
__device__ __nv_bfloat16 g_vtl[(size_t)B_*NH*DH*LK];
__device__ float g_part[(size_t)B_*NH*LQ*32];
__device__ float g_lse [(size_t)B_*NH*LQ];
__device__ float g_ho  [(size_t)B_*LQ*HD];

// pre-transposed hi/lo weights: [n][k]
__device__ __nv_bfloat16 g_wqt_h[HD*DM], g_wqt_l[HD*DM];
__device__ __nv_bfloat16 g_wkt_h[HD*DM], g_wkt_l[HD*DM];
__device__ __nv_bfloat16 g_wvt_h[HD*DM], g_wvt_l[HD*DM];
__device__ __nv_bfloat16 g_wot_h[DM*HD], g_wot_l[DM*HD];

// ---------------- helpers ----------------
__device__ __forceinline__ uint32_t smem_u32(const void* p) {
    uint32_t a;
    asm("{ .reg .u64 t; cvta.to.shared.u64 t, %1; cvt.u32.u64 %0, t; }" : "=r"(a) : "l"(p));
    return a;
}
__device__ __forceinline__ uint32_t pack2(__nv_bfloat16 a, __nv_bfloat16 b) {
    __nv_bfloat162 t; t.x = a; t.y = b;
    return *reinterpret_cast<uint32_t*>(&t);
}

#define LDSM_X4(R0,R1,R2,R3,ADDR) \
    asm volatile("ldmatrix.sync.aligned.m8n8.x4.shared.b16 {%0,%1,%2,%3}, [%4];" \
        : "=r"(R0),"=r"(R1),"=r"(R2),"=r"(R3) : "r"(ADDR))

#define MMA_BF16(C,A0,A1,A2,A3,B0,B1) \
    asm volatile("mma.sync.aligned.m16n8k16.row.col.f32.bf16.bf16.f32 " \
        "{%0,%1,%2,%3}, {%4,%5,%6,%7}, {%8,%9}, {%0,%1,%2,%3};" \
        : "+f"((C)[0]),"+f"((C)[1]),"+f"((C)[2]),"+f"((C)[3]) \
        : "r"(A0),"r"(A1),"r"(A2),"r"(A3),"r"(B0),"r"(B1))

__device__ __forceinline__ float tanh10(float x) {
    x = fminf(fmaxf(x, -15.0f), 15.0f);
    float e = __expf(2.0f * x);
    return 10.0f * __fdividef(e - 1.0f, e + 1.0f);
}

// =====================================================================
// Weight prep: transpose W[K][N] fp32 -> Wt[N][K] bf16 hi/lo.
// grid (N/32, K/32), 256 threads.
// =====================================================================
__global__ __launch_bounds__(256) void wprep(
    const float* __restrict__ W, int K, int N,
    __nv_bfloat16* __restrict__ th, __nv_bfloat16* __restrict__ tl)
{
    __shared__ float ts[32][33];
    int n0 = blockIdx.x * 32, k0 = blockIdx.y * 32;
    int tx = threadIdx.x & 31, ty = threadIdx.x >> 5;
    #pragma unroll
    for (int i = 0; i < 4; ++i) {
        int k = ty + i * 8;
        ts[k][tx] = W[(size_t)(k0 + k) * N + n0 + tx];
    }
    __syncthreads();
    #pragma unroll
    for (int i = 0; i < 4; ++i) {
        int n = ty + i * 8;
        float v = ts[tx][n];
        __nv_bfloat16 h = __float2bfloat16(v);
        th[(size_t)(n0 + n) * K + k0 + tx] = h;
        tl[(size_t)(n0 + n) * K + k0 + tx] = __float2bfloat16(v - __bfloat162float(h));
    }
}

// =====================================================================
// Tensor-core GEMM: C[64 x 128] per block = A(fp32, lda) @ Wt(hi/lo,[n][K]).
// grid (Ntot/128, M/64). modes: 0 = q/k hi/lo out, 1 = v transposed hi/lo,
// 2 = plain fp32 out (+bias).
// smem: ASH 8K | ASL 8K | BSH 16K | BSL 16K  (mode1 overlays ts after loop)
// =====================================================================
__global__ __launch_bounds__(256) void mma_gemm(
    const float* __restrict__ A, int lda, int K,
    const __nv_bfloat16* __restrict__ WtH, const __nv_bfloat16* __restrict__ WtL,
    const float* __restrict__ bias, int mode,
    __nv_bfloat16* __restrict__ oh, __nv_bfloat16* __restrict__ ol,
    float* __restrict__ Cout, int ldc)
{
    extern __shared__ char smem[];
    const uint32_t ASH = 0, ASL = 8192, BSH = 16384, BSL = 32768;
    int tid = threadIdx.x;
    int row0 = blockIdx.y * 64, col0 = blockIdx.x * 128;

    uint32_t sb = smem_u32(smem);
    int w = tid >> 5, lane = tid & 31;
    int wy = w & 3, wx = w >> 2;

    float acc[8][4] = {};

    int arow = wy * 16 + (lane & 15);
    int arx = arow & 7;
    uint32_t aoffH = sb + ASH + (uint32_t)arow * 128;
    uint32_t aoffL = sb + ASL + (uint32_t)arow * 128;
    int ahib = lane >> 4;
    int nrow0 = wx * 64 + (lane & 7) + ((lane & 16) >> 1);
    int bhib = (lane >> 3) & 1;

    int nchunks = K >> 6;
    for (int kc = 0; kc < nchunks; ++kc) {
        // stage A 64x64 fp32 -> hi/lo swizzled
        #pragma unroll
        for (int i = 0; i < 4; ++i) {
            int e = tid + i * 256;               // 0..1023 float4s
            int row = e >> 4, k = (e & 15) * 4;
            float4 av = *reinterpret_cast<const float4*>(
                &A[(size_t)(row0 + row) * lda + kc * 64 + k]);
            __nv_bfloat16 h0 = __float2bfloat16(av.x), h1 = __float2bfloat16(av.y);
            __nv_bfloat16 h2 = __float2bfloat16(av.z), h3 = __float2bfloat16(av.w);
            uint2 hv = make_uint2(pack2(h0, h1), pack2(h2, h3));
            uint2 lv = make_uint2(
                pack2(__float2bfloat16(av.x - __bfloat162float(h0)),
                      __float2bfloat16(av.y - __bfloat162float(h1))),
                pack2(__float2bfloat16(av.z - __bfloat162float(h2)),
                      __float2bfloat16(av.w - __bfloat162float(h3))));
            uint32_t so = (uint32_t)row * 128 + (uint32_t)((((k >> 3)) ^ (row & 7)) << 4)
                        + (uint32_t)((k & 7) * 2);
            *reinterpret_cast<uint2*>(smem + ASH + so) = hv;
            *reinterpret_cast<uint2*>(smem + ASL + so) = lv;
        }
        // stage B (pre-transposed weights) 128n x 64k
        #pragma unroll
        for (int i = 0; i < 4; ++i) {
            int e = tid + i * 256;               // 0..1023
            int n = e >> 3, ch = e & 7;
            size_t go = (size_t)(col0 + n) * K + kc * 64 + ch * 8;
            uint32_t so = (uint32_t)n * 128 + (uint32_t)((ch ^ (n & 7)) << 4);
            *reinterpret_cast<uint4*>(smem + BSH + so) = *reinterpret_cast<const uint4*>(WtH + go);
            *reinterpret_cast<uint4*>(smem + BSL + so) = *reinterpret_cast<const uint4*>(WtL + go);
        }
        __syncthreads();

        #pragma unroll
        for (int s = 0; s < 4; ++s) {
            uint32_t ah[4], al[4];
            uint32_t ac = (uint32_t)(((s * 2 + ahib) ^ arx) << 4);
            LDSM_X4(ah[0], ah[1], ah[2], ah[3], aoffH + ac);
            LDSM_X4(al[0], al[1], al[2], al[3], aoffL + ac);
            #pragma unroll
            for (int g = 0; g < 4; ++g) {
                int r = nrow0 + g * 16;
                uint32_t bo = (uint32_t)r * 128 + (uint32_t)(((s * 2 + bhib) ^ (r & 7)) << 4);
                uint32_t bh[4], bl[4];
                LDSM_X4(bh[0], bh[1], bh[2], bh[3], sb + BSH + bo);
                LDSM_X4(bl[0], bl[1], bl[2], bl[3], sb + BSL + bo);
                #pragma unroll
                for (int t2 = 0; t2 < 2; ++t2) {
                    int nt = g * 2 + t2;
                    MMA_BF16(acc[nt], ah[0], ah[1], ah[2], ah[3], bh[t2 * 2], bh[t2 * 2 + 1]);
                    MMA_BF16(acc[nt], ah[0], ah[1], ah[2], ah[3], bl[t2 * 2], bl[t2 * 2 + 1]);
                    MMA_BF16(acc[nt], al[0], al[1], al[2], al[3], bh[t2 * 2], bh[t2 * 2 + 1]);
                }
            }
        }
        __syncthreads();
    }

    if (mode == 2) {
        int r = row0 + wy * 16 + (lane >> 2);
        #pragma unroll
        for (int nt = 0; nt < 8; ++nt) {
            int c = col0 + wx * 64 + nt * 8 + (lane & 3) * 2;
            float b0 = bias[c], b1 = bias[c + 1];
            *reinterpret_cast<float2*>(&Cout[(size_t)r * ldc + c]) =
                make_float2(acc[nt][0] + b0, acc[nt][1] + b1);
            *reinterpret_cast<float2*>(&Cout[(size_t)(r + 8) * ldc + c]) =
                make_float2(acc[nt][2] + b0, acc[nt][3] + b1);
        }
    } else if (mode == 0) {
        #pragma unroll
        for (int nt = 0; nt < 8; ++nt) {
            int cl = wx * 64 + nt * 8 + (lane & 3) * 2;
            float b0 = bias[cl], b1 = bias[cl + 1];
            int hh = cl >> 6, cc = cl & 63;
            #pragma unroll
            for (int hf = 0; hf < 2; ++hf) {
                int rg = row0 + wy * 16 + hf * 8 + (lane >> 2);
                int b = rg >> 11, r = rg & 2047;
                size_t off = ((size_t)(b * NH + hh) * LQ + r) * 64 + cc;
                float v0 = acc[nt][hf * 2 + 0] + b0;
                float v1 = acc[nt][hf * 2 + 1] + b1;
                __nv_bfloat16 h0 = __float2bfloat16(v0), h1 = __float2bfloat16(v1);
                *reinterpret_cast<uint32_t*>(&oh[off]) = pack2(h0, h1);
                *reinterpret_cast<uint32_t*>(&ol[off]) =
                    pack2(__float2bfloat16(v0 - __bfloat162float(h0)),
                          __float2bfloat16(v1 - __bfloat162float(h1)));
            }
        }
    } else {
        // mode 1 (v): acc -> smem ts fp32, then transposed hi/lo writes
        float* ts = reinterpret_cast<float*>(smem);   // [64][132]
        #pragma unroll
        for (int nt = 0; nt < 8; ++nt) {
            int cl = wx * 64 + nt * 8 + (lane & 3) * 2;
            float b0 = bias[cl], b1 = bias[cl + 1];
            int r = wy * 16 + (lane >> 2);
            ts[r * 132 + cl]           = acc[nt][0] + b0;
            ts[r * 132 + cl + 1]       = acc[nt][1] + b1;
            ts[(r + 8) * 132 + cl]     = acc[nt][2] + b0;
            ts[(r + 8) * 132 + cl + 1] = acc[nt][3] + b1;
        }
        __syncthreads();

        int h2 = tid >> 7, d = (tid >> 1) & 63, seg = tid & 1;
        int b = row0 >> 11;
        int kbase = (row0 & 2047) + seg * 32;
        size_t off = ((size_t)(b * NH + h2) * 64 + d) * (size_t)LK + kbase;
        int c = h2 * 64 + d;
        uint32_t hw[16], lw[16];
        #pragma unroll
        for (int p = 0; p < 16; ++p) {
            float v0 = ts[(seg * 32 + p * 2 + 0) * 132 + c];
            float v1 = ts[(seg * 32 + p * 2 + 1) * 132 + c];
            __nv_bfloat16 h0 = __float2bfloat16(v0), h1 = __float2bfloat16(v1);
            hw[p] = pack2(h0, h1);
            lw[p] = pack2(__float2bfloat16(v0 - __bfloat162float(h0)),
                          __float2bfloat16(v1 - __bfloat162float(h1)));
        }
        #pragma unroll
        for (int u = 0; u < 4; ++u) {
            *reinterpret_cast<uint4*>(&oh[off + u * 8]) =
                make_uint4(hw[u * 4], hw[u * 4 + 1], hw[u * 4 + 2], hw[u * 4 + 3]);
            *reinterpret_cast<uint4*>(&ol[off + u * 8]) =
                make_uint4(lw[u * 4], lw[u * 4 + 1], lw[u * 4 + 2], lw[u * 4 + 3]);
        }
    }
}

// =====================================================================
// QK scores via mma.sync (unchanged core; minBlocks=2 to lift occupancy)
// =====================================================================
__global__ __launch_bounds__(256, 2) void qk_tc(const int* __restrict__ mask,
                                                float* __restrict__ attn)
{
    extern __shared__ char smem[];
    int tid = threadIdx.x;
    int z = blockIdx.z;
    int q0 = blockIdx.y * 128, k0 = blockIdx.x * 128;
    const uint32_t QH = 1024, QL = QH + 16384, KH = QL + 16384, KL = KH + 16384;

    int* smask = reinterpret_cast<int*>(smem);
    if (tid < 128) smask[tid] = mask[(z >> 1) * LK + k0 + tid];

    {
        size_t qrow = (size_t)z * LQ + q0;
        size_t krow = (size_t)z * LK + k0;
        #pragma unroll
        for (int i = 0; i < 4; ++i) {
            int idx = tid + i * 256;
            int row = idx >> 3, ch = idx & 7;
            uint32_t so = (uint32_t)row * 128 + (uint32_t)((ch ^ (row & 7)) << 4);
            size_t go = (qrow + row) * 64 + ch * 8;
            size_t gk = (krow + row) * 64 + ch * 8;
            *reinterpret_cast<uint4*>(smem + QH + so) = *reinterpret_cast<const uint4*>(g_qh + go);
            *reinterpret_cast<uint4*>(smem + QL + so) = *reinterpret_cast<const uint4*>(g_ql + go);
            *reinterpret_cast<uint4*>(smem + KH + so) = *reinterpret_cast<const uint4*>(g_kh + gk);
            *reinterpret_cast<uint4*>(smem + KL + so) = *reinterpret_cast<const uint4*>(g_kl + gk);
        }
    }
    __syncthreads();

    uint32_t sb = smem_u32(smem);
    int w = tid >> 5, lane = tid & 31;
    int wy = w & 3, wx = w >> 2;

    float acc[2][8][4] = {};

    uint32_t aoffH[2], aoffL[2];
    int arx[2];
    #pragma unroll
    for (int mt = 0; mt < 2; ++mt) {
        int r = wy * 32 + mt * 16 + (lane & 15);
        arx[mt] = r & 7;
        aoffH[mt] = sb + QH + (uint32_t)r * 128;
        aoffL[mt] = sb + QL + (uint32_t)r * 128;
    }
    int ahib = lane >> 4;
    int nrow0 = wx * 64 + (lane & 7) + ((lane & 16) >> 1);
    int bhib = (lane >> 3) & 1;

    #pragma unroll
    for (int s = 0; s < 4; ++s) {
        uint32_t ah[2][4], al[2][4];
        #pragma unroll
        for (int mt = 0; mt < 2; ++mt) {
            uint32_t c = (uint32_t)(((s * 2 + ahib) ^ arx[mt]) << 4);
            LDSM_X4(ah[mt][0], ah[mt][1], ah[mt][2], ah[mt][3], aoffH[mt] + c);
            LDSM_X4(al[mt][0], al[mt][1], al[mt][2], al[mt][3], aoffL[mt] + c);
        }
        #pragma unroll
        for (int g = 0; g < 4; ++g) {
            int r = nrow0 + g * 16;
            uint32_t bo = (uint32_t)r * 128 + (uint32_t)(((s * 2 + bhib) ^ (r & 7)) << 4);
            uint32_t bh[4], bl[4];
            LDSM_X4(bh[0], bh[1], bh[2], bh[3], sb + KH + bo);
            LDSM_X4(bl[0], bl[1], bl[2], bl[3], sb + KL + bo);
            #pragma unroll
            for (int t2 = 0; t2 < 2; ++t2) {
                int nt = g * 2 + t2;
                #pragma unroll
                for (int mt = 0; mt < 2; ++mt) {
                    MMA_BF16(acc[mt][nt], ah[mt][0], ah[mt][1], ah[mt][2], ah[mt][3],
                             bh[t2 * 2], bh[t2 * 2 + 1]);
                    MMA_BF16(acc[mt][nt], ah[mt][0], ah[mt][1], ah[mt][2], ah[mt][3],
                             bl[t2 * 2], bl[t2 * 2 + 1]);
                    MMA_BF16(acc[mt][nt], al[mt][0], al[mt][1], al[mt][2], al[mt][3],
                             bh[t2 * 2], bh[t2 * 2 + 1]);
                }
            }
        }
    }

    float rs[2][2] = {};
    #pragma unroll
    for (int mt = 0; mt < 2; ++mt) {
        int r = q0 + wy * 32 + mt * 16 + (lane >> 2);
        float* row0p = attn + (size_t)z * LQ * LK + (size_t)r * LK + k0;
        float* row1p = row0p + (size_t)8 * LK;
        #pragma unroll
        for (int nt = 0; nt < 8; ++nt) {
            int cl = wx * 64 + nt * 8 + (lane & 3) * 2;
            int m0 = smask[cl], m1 = smask[cl + 1];
            float s0 = tanh10(acc[mt][nt][0] * 0.125f);
            float s1 = tanh10(acc[mt][nt][1] * 0.125f);
            float s2 = tanh10(acc[mt][nt][2] * 0.125f);
            float s3 = tanh10(acc[mt][nt][3] * 0.125f);
            if (m0) { s0 = -10.0f; s2 = -10.0f; }
            if (m1) { s1 = -10.0f; s3 = -10.0f; }
            *reinterpret_cast<float2*>(row0p + cl) = make_float2(s0, s1);
            *reinterpret_cast<float2*>(row1p + cl) = make_float2(s2, s3);
            rs[mt][0] += __expf(s0) + __expf(s1);
            rs[mt][1] += __expf(s2) + __expf(s3);
        }
    }
    #pragma unroll
    for (int mt = 0; mt < 2; ++mt)
        #pragma unroll
        for (int hf = 0; hf < 2; ++hf) {
            float v = rs[mt][hf];
            v += __shfl_xor_sync(0xffffffffu, v, 1);
            v += __shfl_xor_sync(0xffffffffu, v, 2);
            rs[mt][hf] = v;
        }
    if ((lane & 3) == 0) {
        int col = blockIdx.x * 2 + wx;
        #pragma unroll
        for (int mt = 0; mt < 2; ++mt)
            #pragma unroll
            for (int hf = 0; hf < 2; ++hf) {
                int r = q0 + wy * 32 + mt * 16 + hf * 8 + (lane >> 2);
                g_part[((size_t)z * LQ + r) * 32 + col] = rs[mt][hf];
            }
    }
}

// =====================================================================
__global__ __launch_bounds__(256) void lse_reduce()
{
    int r = blockIdx.x * 256 + threadIdx.x;
    float s = 0.0f;
    #pragma unroll
    for (int j = 0; j < 32; ++j) s += g_part[(size_t)r * 32 + j];
    g_lse[r] = logf(s);
}

// =====================================================================
// PV via mma.sync (unchanged from R10)
// =====================================================================
__global__ __launch_bounds__(256) void pv_tc(float* __restrict__ attn)
{
    extern __shared__ char smem[];
    int tid = threadIdx.x;
    int z = blockIdx.y, q0 = blockIdx.x * 64;
    const uint32_t AH = 1024, AL = AH + 8192, VH = AL + 8192, VL = VH + 8192;

    float* s_lse = reinterpret_cast<float*>(smem);
    if (tid < 64) s_lse[tid] = g_lse[(size_t)z * LQ + q0 + tid];
    __syncthreads();

    uint32_t sb = smem_u32(smem);
    int w = tid >> 5, lane = tid & 31;
    int wy = w & 3, wx = w >> 2;
    float acc[4][4] = {};

    int arow = wy * 16 + (lane & 15);
    int arx = arow & 7;
    uint32_t aoffH = sb + AH + (uint32_t)arow * 128;
    uint32_t aoffL = sb + AL + (uint32_t)arow * 128;
    int ahib = lane >> 4;
    int nrow0 = wx * 32 + (lane & 7) + ((lane & 16) >> 1);
    int bhib = (lane >> 3) & 1;

    float* abase = attn + (size_t)z * LQ * LK + (size_t)q0 * LK;

    for (int kc = 0; kc < 32; ++kc) {
        int k0 = kc * 64;

        #pragma unroll
        for (int i = 0; i < 4; ++i) {
            int idx = tid + i * 256;
            int row = idx >> 4, pos = idx & 15;
            float* ap = abase + (size_t)row * LK + k0 + pos * 4;
            float4 sv = *reinterpret_cast<float4*>(ap);
            float l = s_lse[row];
            float a0 = sv.x - l, a1 = sv.y - l, a2 = sv.z - l, a3 = sv.w - l;
            *reinterpret_cast<float4*>(ap) = make_float4(a0, a1, a2, a3);
            __nv_bfloat16 h0 = __float2bfloat16(a0), h1 = __float2bfloat16(a1);
            __nv_bfloat16 h2 = __float2bfloat16(a2), h3 = __float2bfloat16(a3);
            uint2 hv = make_uint2(pack2(h0, h1), pack2(h2, h3));
            uint2 lv = make_uint2(
                pack2(__float2bfloat16(a0 - __bfloat162float(h0)),
                      __float2bfloat16(a1 - __bfloat162float(h1))),
                pack2(__float2bfloat16(a2 - __bfloat162float(h2)),
                      __float2bfloat16(a3 - __bfloat162float(h3))));
            int ch = pos >> 1, half = pos & 1;
            uint32_t so = (uint32_t)row * 128 + (uint32_t)((ch ^ (row & 7)) << 4) + half * 8;
            *reinterpret_cast<uint2*>(smem + AH + so) = hv;
            *reinterpret_cast<uint2*>(smem + AL + so) = lv;
        }
        #pragma unroll
        for (int i = 0; i < 2; ++i) {
            int idx = tid + i * 256;
            int row = idx >> 3, ch = idx & 7;
            size_t go = ((size_t)z * 64 + row) * (size_t)LK + k0 + ch * 8;
            uint32_t so = (uint32_t)row * 128 + (uint32_t)((ch ^ (row & 7)) << 4);
            *reinterpret_cast<uint4*>(smem + VH + so) = *reinterpret_cast<const uint4*>(g_vth + go);
            *reinterpret_cast<uint4*>(smem + VL + so) = *reinterpret_cast<const uint4*>(g_vtl + go);
        }
        __syncthreads();

        #pragma unroll
        for (int s = 0; s < 4; ++s) {
            uint32_t ah[4], al[4];
            uint32_t ac = (uint32_t)(((s * 2 + ahib) ^ arx) << 4);
            LDSM_X4(ah[0], ah[1], ah[2], ah[3], aoffH + ac);
            LDSM_X4(al[0], al[1], al[2], al[3], aoffL + ac);
            #pragma unroll
            for (int g = 0; g < 2; ++g) {
                int r = nrow0 + g * 16;
                uint32_t bo = (uint32_t)r * 128 + (uint32_t)(((s * 2 + bhib) ^ (r & 7)) << 4);
                uint32_t bh[4], bl[4];
                LDSM_X4(bh[0], bh[1], bh[2], bh[3], sb + VH + bo);
                LDSM_X4(bl[0], bl[1], bl[2], bl[3], sb + VL + bo);
                #pragma unroll
                for (int t2 = 0; t2 < 2; ++t2) {
                    int nt = g * 2 + t2;
                    MMA_BF16(acc[nt], ah[0], ah[1], ah[2], ah[3], bh[t2 * 2], bh[t2 * 2 + 1]);
                    MMA_BF16(acc[nt], ah[0], ah[1], ah[2], ah[3], bl[t2 * 2], bl[t2 * 2 + 1]);
                    MMA_BF16(acc[nt], al[0], al[1], al[2], al[3], bh[t2 * 2], bh[t2 * 2 + 1]);
                }
            }
        }
        __syncthreads();
    }

    int b = z >> 1, h = z & 1;
    int r0 = q0 + wy * 16 + (lane >> 2);
    float* d0 = g_ho + ((size_t)b * LQ + r0) * HD + h * 64 + wx * 32 + (lane & 3) * 2;
    float* d1 = d0 + (size_t)8 * HD;
    #pragma unroll
    for (int nt = 0; nt < 4; ++nt) {
        *reinterpret_cast<float2*>(d0 + nt * 8) = make_float2(acc[nt][0], acc[nt][1]);
        *reinterpret_cast<float2*>(d1 + nt * 8) = make_float2(acc[nt][2], acc[nt][3]);
    }
}

// =====================================================================
extern "C" void kernel_launch(void* const* d_in, const int* in_sizes, int n_in,
                              void* d_out, int out_size)
{
    const float* Q    = (const float*)d_in[0];
    const float* K    = (const float*)d_in[1];
    const float* V    = (const float*)d_in[2];
    const int*   mask = (const int*)  d_in[3];
    const float* Wq   = (const float*)d_in[4];
    const float* bq   = (const float*)d_in[5];
    const float* Wk   = (const float*)d_in[6];
    const float* bk   = (const float*)d_in[7];
    const float* Wv   = (const float*)d_in[8];
    const float* bv   = (const float*)d_in[9];
    const float* Wo   = (const float*)d_in[10];
    const float* bo   = (const float*)d_in[11];

    float* out  = (float*)d_out;
    float* attn = out + (size_t)B_ * LQ * DM;

    __nv_bfloat16 *qh, *ql, *kh, *kl, *vth, *vtl;
    __nv_bfloat16 *wqh, *wql, *wkh, *wkl, *wvh, *wvl, *woh, *wol;
    float *gho;
    cudaGetSymbolAddress((void**)&qh,  g_qh);
    cudaGetSymbolAddress((void**)&ql,  g_ql);
    cudaGetSymbolAddress((void**)&kh,  g_kh);
    cudaGetSymbolAddress((void**)&kl,  g_kl);
    cudaGetSymbolAddress((void**)&vth, g_vth);
    cudaGetSymbolAddress((void**)&vtl, g_vtl);
    cudaGetSymbolAddress((void**)&gho, g_ho);
    cudaGetSymbolAddress((void**)&wqh, g_wqt_h);
    cudaGetSymbolAddress((void**)&wql, g_wqt_l);
    cudaGetSymbolAddress((void**)&wkh, g_wkt_h);
    cudaGetSymbolAddress((void**)&wkl, g_wkt_l);
    cudaGetSymbolAddress((void**)&wvh, g_wvt_h);
    cudaGetSymbolAddress((void**)&wvl, g_wvt_l);
    cudaGetSymbolAddress((void**)&woh, g_wot_h);
    cudaGetSymbolAddress((void**)&wol, g_wot_l);

    cudaFuncSetAttribute(qk_tc,    cudaFuncAttributeMaxDynamicSharedMemorySize, 66560);
    cudaFuncSetAttribute(pv_tc,    cudaFuncAttributeMaxDynamicSharedMemorySize, 33792);
    cudaFuncSetAttribute(mma_gemm, cudaFuncAttributeMaxDynamicSharedMemorySize, 49152);

    // weight prep
    wprep<<<dim3(HD / 32, DM / 32), 256>>>(Wq, DM, HD, wqh, wql);
    wprep<<<dim3(HD / 32, DM / 32), 256>>>(Wk, DM, HD, wkh, wkl);
    wprep<<<dim3(HD / 32, DM / 32), 256>>>(Wv, DM, HD, wvh, wvl);
    wprep<<<dim3(DM / 32, HD / 32), 256>>>(Wo, HD, DM, woh, wol);

    // projections (tensor)
    mma_gemm<<<dim3(1, (B_ * LQ) / 64), 256, 49152>>>(
        Q, DM, DM, wqh, wql, bq, 0, qh, ql, (float*)0, 0);
    mma_gemm<<<dim3(1, (B_ * LQ) / 64), 256, 49152>>>(
        K, DM, DM, wkh, wkl, bk, 0, kh, kl, (float*)0, 0);
    mma_gemm<<<dim3(1, (B_ * LQ) / 64), 256, 49152>>>(
        V, DM, DM, wvh, wvl, bv, 1, vth, vtl, (float*)0, 0);

    qk_tc<<<dim3(LK / 128, LQ / 128, B_ * NH), 256, 66560>>>(mask, attn);

    lse_reduce<<<(B_ * NH * LQ) / 256, 256>>>();

    pv_tc<<<dim3(LQ / 64, B_ * NH), 256, 33792>>>(attn);

    // out projection (tensor)
    mma_gemm<<<dim3(DM / 128, (B_ * LQ) / 64), 256, 49152>>>(
        gho, HD, HD, woh, wol, bo, 2, (__nv_bfloat16*)0, (__nv_bfloat16*)0, out, DM);
}

// round 13
// speedup vs baseline: 3.4308x; 1.2650x over previous
#include <cuda_runtime.h>
#include <cuda_bf16.h>
#include <math.h>
#include <stdint.h>

#define B_ 4
#define LQ 2048
#define LK 2048
#define DM 512
#define NH 2
#define DH 64
#define HD 128   /* NH*DH */

// ---------------- scratch (device globals; no allocation) ----------------
__device__ __nv_bfloat16 g_qh[(size_t)B_*NH*LQ*DH];
__device__ __nv_bfloat16 g_ql[(size_t)B_*NH*LQ*DH];
__device__ __nv_bfloat16 g_kh[(size_t)B_*NH*LK*DH];
__device__ __nv_bfloat16 g_kl[(size_t)B_*NH*LK*DH];
__device__ __nv_bfloat16 g_vth[(size_t)B_*NH*DH*LK];   // v transposed: [z][d][k]
__device__ __nv_bfloat16 g_vtl[(size_t)B_*NH*DH*LK];
__device__ float g_part[(size_t)B_*NH*LQ*32];
__device__ float g_lse [(size_t)B_*NH*LQ];
__device__ float g_ho  [(size_t)B_*LQ*HD];

// pre-transposed hi/lo weights: [n][k]
__device__ __nv_bfloat16 g_wqt_h[HD*DM], g_wqt_l[HD*DM];
__device__ __nv_bfloat16 g_wkt_h[HD*DM], g_wkt_l[HD*DM];
__device__ __nv_bfloat16 g_wvt_h[HD*DM], g_wvt_l[HD*DM];
__device__ __nv_bfloat16 g_wot_h[DM*HD], g_wot_l[DM*HD];

// ---------------- helpers ----------------
__device__ __forceinline__ uint32_t smem_u32(const void* p) {
    uint32_t a;
    asm("{ .reg .u64 t; cvta.to.shared.u64 t, %1; cvt.u32.u64 %0, t; }" : "=r"(a) : "l"(p));
    return a;
}
__device__ __forceinline__ uint32_t pack2(__nv_bfloat16 a, __nv_bfloat16 b) {
    __nv_bfloat162 t; t.x = a; t.y = b;
    return *reinterpret_cast<uint32_t*>(&t);
}

#define LDSM_X4(R0,R1,R2,R3,ADDR) \
    asm volatile("ldmatrix.sync.aligned.m8n8.x4.shared.b16 {%0,%1,%2,%3}, [%4];" \
        : "=r"(R0),"=r"(R1),"=r"(R2),"=r"(R3) : "r"(ADDR))

#define MMA_BF16(C,A0,A1,A2,A3,B0,B1) \
    asm volatile("mma.sync.aligned.m16n8k16.row.col.f32.bf16.bf16.f32 " \
        "{%0,%1,%2,%3}, {%4,%5,%6,%7}, {%8,%9}, {%0,%1,%2,%3};" \
        : "+f"((C)[0]),"+f"((C)[1]),"+f"((C)[2]),"+f"((C)[3]) \
        : "r"(A0),"r"(A1),"r"(A2),"r"(A3),"r"(B0),"r"(B1))

__device__ __forceinline__ float tanh10(float x) {
    x = fminf(fmaxf(x, -15.0f), 15.0f);
    float e = __expf(2.0f * x);
    return 10.0f * __fdividef(e - 1.0f, e + 1.0f);
}

// =====================================================================
// Weight prep (all 4 weights in ONE launch): W[K][N] fp32 -> Wt[N][K] hi/lo
// grid (16, 16, 4); blocks outside each weight's range early-out.
// =====================================================================
__global__ __launch_bounds__(256) void wprep_all(
    const float* __restrict__ Wq, const float* __restrict__ Wk,
    const float* __restrict__ Wv, const float* __restrict__ Wo)
{
    __shared__ float ts[32][33];
    int z = blockIdx.z;
    const float* W;
    __nv_bfloat16 *th, *tl;
    int K, N;
    if (z == 0)      { W = Wq; th = g_wqt_h; tl = g_wqt_l; K = DM; N = HD; }
    else if (z == 1) { W = Wk; th = g_wkt_h; tl = g_wkt_l; K = DM; N = HD; }
    else if (z == 2) { W = Wv; th = g_wvt_h; tl = g_wvt_l; K = DM; N = HD; }
    else             { W = Wo; th = g_wot_h; tl = g_wot_l; K = HD; N = DM; }

    int n0 = blockIdx.x * 32, k0 = blockIdx.y * 32;
    if (n0 >= N || k0 >= K) return;

    int tx = threadIdx.x & 31, ty = threadIdx.x >> 5;
    #pragma unroll
    for (int i = 0; i < 4; ++i) {
        int k = ty + i * 8;
        ts[k][tx] = W[(size_t)(k0 + k) * N + n0 + tx];
    }
    __syncthreads();
    #pragma unroll
    for (int i = 0; i < 4; ++i) {
        int n = ty + i * 8;
        float v = ts[tx][n];
        __nv_bfloat16 h = __float2bfloat16(v);
        th[(size_t)(n0 + n) * K + k0 + tx] = h;
        tl[(size_t)(n0 + n) * K + k0 + tx] = __float2bfloat16(v - __bfloat162float(h));
    }
}

// =====================================================================
// Tensor-core GEMM: C[64 x 128] per block = A(fp32, lda) @ Wt(hi/lo,[n][K]).
// modes: 0 = q/k hi/lo out, 1 = v transposed hi/lo, 2 = fp32 out (+bias).
// =====================================================================
__global__ __launch_bounds__(256) void mma_gemm(
    const float* __restrict__ A, int lda, int K,
    const __nv_bfloat16* __restrict__ WtH, const __nv_bfloat16* __restrict__ WtL,
    const float* __restrict__ bias, int mode,
    __nv_bfloat16* __restrict__ oh, __nv_bfloat16* __restrict__ ol,
    float* __restrict__ Cout, int ldc)
{
    extern __shared__ char smem[];
    const uint32_t ASH = 0, ASL = 8192, BSH = 16384, BSL = 32768;
    int tid = threadIdx.x;
    int row0 = blockIdx.y * 64, col0 = blockIdx.x * 128;

    uint32_t sb = smem_u32(smem);
    int w = tid >> 5, lane = tid & 31;
    int wy = w & 3, wx = w >> 2;

    float acc[8][4] = {};

    int arow = wy * 16 + (lane & 15);
    int arx = arow & 7;
    uint32_t aoffH = sb + ASH + (uint32_t)arow * 128;
    uint32_t aoffL = sb + ASL + (uint32_t)arow * 128;
    int ahib = lane >> 4;
    int nrow0 = wx * 64 + (lane & 7) + ((lane & 16) >> 1);
    int bhib = (lane >> 3) & 1;

    int nchunks = K >> 6;
    for (int kc = 0; kc < nchunks; ++kc) {
        #pragma unroll
        for (int i = 0; i < 4; ++i) {
            int e = tid + i * 256;
            int row = e >> 4, k = (e & 15) * 4;
            float4 av = *reinterpret_cast<const float4*>(
                &A[(size_t)(row0 + row) * lda + kc * 64 + k]);
            __nv_bfloat16 h0 = __float2bfloat16(av.x), h1 = __float2bfloat16(av.y);
            __nv_bfloat16 h2 = __float2bfloat16(av.z), h3 = __float2bfloat16(av.w);
            uint2 hv = make_uint2(pack2(h0, h1), pack2(h2, h3));
            uint2 lv = make_uint2(
                pack2(__float2bfloat16(av.x - __bfloat162float(h0)),
                      __float2bfloat16(av.y - __bfloat162float(h1))),
                pack2(__float2bfloat16(av.z - __bfloat162float(h2)),
                      __float2bfloat16(av.w - __bfloat162float(h3))));
            uint32_t so = (uint32_t)row * 128 + (uint32_t)((((k >> 3)) ^ (row & 7)) << 4)
                        + (uint32_t)((k & 7) * 2);
            *reinterpret_cast<uint2*>(smem + ASH + so) = hv;
            *reinterpret_cast<uint2*>(smem + ASL + so) = lv;
        }
        #pragma unroll
        for (int i = 0; i < 4; ++i) {
            int e = tid + i * 256;
            int n = e >> 3, ch = e & 7;
            size_t go = (size_t)(col0 + n) * K + kc * 64 + ch * 8;
            uint32_t so = (uint32_t)n * 128 + (uint32_t)((ch ^ (n & 7)) << 4);
            *reinterpret_cast<uint4*>(smem + BSH + so) = *reinterpret_cast<const uint4*>(WtH + go);
            *reinterpret_cast<uint4*>(smem + BSL + so) = *reinterpret_cast<const uint4*>(WtL + go);
        }
        __syncthreads();

        #pragma unroll
        for (int s = 0; s < 4; ++s) {
            uint32_t ah[4], al[4];
            uint32_t ac = (uint32_t)(((s * 2 + ahib) ^ arx) << 4);
            LDSM_X4(ah[0], ah[1], ah[2], ah[3], aoffH + ac);
            LDSM_X4(al[0], al[1], al[2], al[3], aoffL + ac);
            #pragma unroll
            for (int g = 0; g < 4; ++g) {
                int r = nrow0 + g * 16;
                uint32_t bo = (uint32_t)r * 128 + (uint32_t)(((s * 2 + bhib) ^ (r & 7)) << 4);
                uint32_t bh[4], bl[4];
                LDSM_X4(bh[0], bh[1], bh[2], bh[3], sb + BSH + bo);
                LDSM_X4(bl[0], bl[1], bl[2], bl[3], sb + BSL + bo);
                #pragma unroll
                for (int t2 = 0; t2 < 2; ++t2) {
                    int nt = g * 2 + t2;
                    MMA_BF16(acc[nt], ah[0], ah[1], ah[2], ah[3], bh[t2 * 2], bh[t2 * 2 + 1]);
                    MMA_BF16(acc[nt], ah[0], ah[1], ah[2], ah[3], bl[t2 * 2], bl[t2 * 2 + 1]);
                    MMA_BF16(acc[nt], al[0], al[1], al[2], al[3], bh[t2 * 2], bh[t2 * 2 + 1]);
                }
            }
        }
        __syncthreads();
    }

    if (mode == 2) {
        int r = row0 + wy * 16 + (lane >> 2);
        #pragma unroll
        for (int nt = 0; nt < 8; ++nt) {
            int c = col0 + wx * 64 + nt * 8 + (lane & 3) * 2;
            float b0 = bias[c], b1 = bias[c + 1];
            *reinterpret_cast<float2*>(&Cout[(size_t)r * ldc + c]) =
                make_float2(acc[nt][0] + b0, acc[nt][1] + b1);
            *reinterpret_cast<float2*>(&Cout[(size_t)(r + 8) * ldc + c]) =
                make_float2(acc[nt][2] + b0, acc[nt][3] + b1);
        }
    } else if (mode == 0) {
        #pragma unroll
        for (int nt = 0; nt < 8; ++nt) {
            int cl = wx * 64 + nt * 8 + (lane & 3) * 2;
            float b0 = bias[cl], b1 = bias[cl + 1];
            int hh = cl >> 6, cc = cl & 63;
            #pragma unroll
            for (int hf = 0; hf < 2; ++hf) {
                int rg = row0 + wy * 16 + hf * 8 + (lane >> 2);
                int b = rg >> 11, r = rg & 2047;
                size_t off = ((size_t)(b * NH + hh) * LQ + r) * 64 + cc;
                float v0 = acc[nt][hf * 2 + 0] + b0;
                float v1 = acc[nt][hf * 2 + 1] + b1;
                __nv_bfloat16 h0 = __float2bfloat16(v0), h1 = __float2bfloat16(v1);
                *reinterpret_cast<uint32_t*>(&oh[off]) = pack2(h0, h1);
                *reinterpret_cast<uint32_t*>(&ol[off]) =
                    pack2(__float2bfloat16(v0 - __bfloat162float(h0)),
                          __float2bfloat16(v1 - __bfloat162float(h1)));
            }
        }
    } else {
        float* ts = reinterpret_cast<float*>(smem);   // [64][132]
        #pragma unroll
        for (int nt = 0; nt < 8; ++nt) {
            int cl = wx * 64 + nt * 8 + (lane & 3) * 2;
            float b0 = bias[cl], b1 = bias[cl + 1];
            int r = wy * 16 + (lane >> 2);
            ts[r * 132 + cl]           = acc[nt][0] + b0;
            ts[r * 132 + cl + 1]       = acc[nt][1] + b1;
            ts[(r + 8) * 132 + cl]     = acc[nt][2] + b0;
            ts[(r + 8) * 132 + cl + 1] = acc[nt][3] + b1;
        }
        __syncthreads();

        int h2 = tid >> 7, d = (tid >> 1) & 63, seg = tid & 1;
        int b = row0 >> 11;
        int kbase = (row0 & 2047) + seg * 32;
        size_t off = ((size_t)(b * NH + h2) * 64 + d) * (size_t)LK + kbase;
        int c = h2 * 64 + d;
        uint32_t hw[16], lw[16];
        #pragma unroll
        for (int p = 0; p < 16; ++p) {
            float v0 = ts[(seg * 32 + p * 2 + 0) * 132 + c];
            float v1 = ts[(seg * 32 + p * 2 + 1) * 132 + c];
            __nv_bfloat16 h0 = __float2bfloat16(v0), h1 = __float2bfloat16(v1);
            hw[p] = pack2(h0, h1);
            lw[p] = pack2(__float2bfloat16(v0 - __bfloat162float(h0)),
                          __float2bfloat16(v1 - __bfloat162float(h1)));
        }
        #pragma unroll
        for (int u = 0; u < 4; ++u) {
            *reinterpret_cast<uint4*>(&g_vth[off + u * 8]) =
                make_uint4(hw[u * 4], hw[u * 4 + 1], hw[u * 4 + 2], hw[u * 4 + 3]);
            *reinterpret_cast<uint4*>(&g_vtl[off + u * 8]) =
                make_uint4(lw[u * 4], lw[u * 4 + 1], lw[u * 4 + 2], lw[u * 4 + 3]);
        }
    }
}

// =====================================================================
// QK scores via mma.sync (unchanged from R11)
// =====================================================================
__global__ __launch_bounds__(256, 2) void qk_tc(const int* __restrict__ mask,
                                                float* __restrict__ attn)
{
    extern __shared__ char smem[];
    int tid = threadIdx.x;
    int z = blockIdx.z;
    int q0 = blockIdx.y * 128, k0 = blockIdx.x * 128;
    const uint32_t QH = 1024, QL = QH + 16384, KH = QL + 16384, KL = KH + 16384;

    int* smask = reinterpret_cast<int*>(smem);
    if (tid < 128) smask[tid] = mask[(z >> 1) * LK + k0 + tid];

    {
        size_t qrow = (size_t)z * LQ + q0;
        size_t krow = (size_t)z * LK + k0;
        #pragma unroll
        for (int i = 0; i < 4; ++i) {
            int idx = tid + i * 256;
            int row = idx >> 3, ch = idx & 7;
            uint32_t so = (uint32_t)row * 128 + (uint32_t)((ch ^ (row & 7)) << 4);
            size_t go = (qrow + row) * 64 + ch * 8;
            size_t gk = (krow + row) * 64 + ch * 8;
            *reinterpret_cast<uint4*>(smem + QH + so) = *reinterpret_cast<const uint4*>(g_qh + go);
            *reinterpret_cast<uint4*>(smem + QL + so) = *reinterpret_cast<const uint4*>(g_ql + go);
            *reinterpret_cast<uint4*>(smem + KH + so) = *reinterpret_cast<const uint4*>(g_kh + gk);
            *reinterpret_cast<uint4*>(smem + KL + so) = *reinterpret_cast<const uint4*>(g_kl + gk);
        }
    }
    __syncthreads();

    uint32_t sb = smem_u32(smem);
    int w = tid >> 5, lane = tid & 31;
    int wy = w & 3, wx = w >> 2;

    float acc[2][8][4] = {};

    uint32_t aoffH[2], aoffL[2];
    int arx[2];
    #pragma unroll
    for (int mt = 0; mt < 2; ++mt) {
        int r = wy * 32 + mt * 16 + (lane & 15);
        arx[mt] = r & 7;
        aoffH[mt] = sb + QH + (uint32_t)r * 128;
        aoffL[mt] = sb + QL + (uint32_t)r * 128;
    }
    int ahib = lane >> 4;
    int nrow0 = wx * 64 + (lane & 7) + ((lane & 16) >> 1);
    int bhib = (lane >> 3) & 1;

    #pragma unroll
    for (int s = 0; s < 4; ++s) {
        uint32_t ah[2][4], al[2][4];
        #pragma unroll
        for (int mt = 0; mt < 2; ++mt) {
            uint32_t c = (uint32_t)(((s * 2 + ahib) ^ arx[mt]) << 4);
            LDSM_X4(ah[mt][0], ah[mt][1], ah[mt][2], ah[mt][3], aoffH[mt] + c);
            LDSM_X4(al[mt][0], al[mt][1], al[mt][2], al[mt][3], aoffL[mt] + c);
        }
        #pragma unroll
        for (int g = 0; g < 4; ++g) {
            int r = nrow0 + g * 16;
            uint32_t bo = (uint32_t)r * 128 + (uint32_t)(((s * 2 + bhib) ^ (r & 7)) << 4);
            uint32_t bh[4], bl[4];
            LDSM_X4(bh[0], bh[1], bh[2], bh[3], sb + KH + bo);
            LDSM_X4(bl[0], bl[1], bl[2], bl[3], sb + KL + bo);
            #pragma unroll
            for (int t2 = 0; t2 < 2; ++t2) {
                int nt = g * 2 + t2;
                #pragma unroll
                for (int mt = 0; mt < 2; ++mt) {
                    MMA_BF16(acc[mt][nt], ah[mt][0], ah[mt][1], ah[mt][2], ah[mt][3],
                             bh[t2 * 2], bh[t2 * 2 + 1]);
                    MMA_BF16(acc[mt][nt], ah[mt][0], ah[mt][1], ah[mt][2], ah[mt][3],
                             bl[t2 * 2], bl[t2 * 2 + 1]);
                    MMA_BF16(acc[mt][nt], al[mt][0], al[mt][1], al[mt][2], al[mt][3],
                             bh[t2 * 2], bh[t2 * 2 + 1]);
                }
            }
        }
    }

    float rs[2][2] = {};
    #pragma unroll
    for (int mt = 0; mt < 2; ++mt) {
        int r = q0 + wy * 32 + mt * 16 + (lane >> 2);
        float* row0p = attn + (size_t)z * LQ * LK + (size_t)r * LK + k0;
        float* row1p = row0p + (size_t)8 * LK;
        #pragma unroll
        for (int nt = 0; nt < 8; ++nt) {
            int cl = wx * 64 + nt * 8 + (lane & 3) * 2;
            int m0 = smask[cl], m1 = smask[cl + 1];
            float s0 = tanh10(acc[mt][nt][0] * 0.125f);
            float s1 = tanh10(acc[mt][nt][1] * 0.125f);
            float s2 = tanh10(acc[mt][nt][2] * 0.125f);
            float s3 = tanh10(acc[mt][nt][3] * 0.125f);
            if (m0) { s0 = -10.0f; s2 = -10.0f; }
            if (m1) { s1 = -10.0f; s3 = -10.0f; }
            *reinterpret_cast<float2*>(row0p + cl) = make_float2(s0, s1);
            *reinterpret_cast<float2*>(row1p + cl) = make_float2(s2, s3);
            rs[mt][0] += __expf(s0) + __expf(s1);
            rs[mt][1] += __expf(s2) + __expf(s3);
        }
    }
    #pragma unroll
    for (int mt = 0; mt < 2; ++mt)
        #pragma unroll
        for (int hf = 0; hf < 2; ++hf) {
            float v = rs[mt][hf];
            v += __shfl_xor_sync(0xffffffffu, v, 1);
            v += __shfl_xor_sync(0xffffffffu, v, 2);
            rs[mt][hf] = v;
        }
    if ((lane & 3) == 0) {
        int col = blockIdx.x * 2 + wx;
        #pragma unroll
        for (int mt = 0; mt < 2; ++mt)
            #pragma unroll
            for (int hf = 0; hf < 2; ++hf) {
                int r = q0 + wy * 32 + mt * 16 + hf * 8 + (lane >> 2);
                g_part[((size_t)z * LQ + r) * 32 + col] = rs[mt][hf];
            }
    }
}

// =====================================================================
__global__ __launch_bounds__(256) void lse_reduce()
{
    int r = blockIdx.x * 256 + threadIdx.x;
    float s = 0.0f;
    #pragma unroll
    for (int j = 0; j < 32; ++j) s += g_part[(size_t)r * 32 + j];
    g_lse[r] = logf(s);
}

// =====================================================================
// PV via mma.sync — register-prefetch pipeline + 2 blocks/SM.
// Per chunk: convert prefetched regs -> (normalized global write + hi/lo
// smem), sync, prefetch next chunk (overlaps MMA), MMA, sync.
// =====================================================================
#define PV_LOAD_CHUNK(K0)                                                          \
    do {                                                                           \
        _Pragma("unroll")                                                          \
        for (int i = 0; i < 4; ++i) {                                              \
            int idx = tid + i * 256;                                               \
            int row = idx >> 4, pos = idx & 15;                                    \
            pa[i] = *reinterpret_cast<const float4*>(                              \
                abase + (size_t)row * LK + (K0) + pos * 4);                        \
        }                                                                          \
        _Pragma("unroll")                                                          \
        for (int i = 0; i < 2; ++i) {                                              \
            int idx = tid + i * 256;                                               \
            int row = idx >> 3, ch = idx & 7;                                      \
            size_t go = ((size_t)z * 64 + row) * (size_t)LK + (K0) + ch * 8;       \
            pvh[i] = *reinterpret_cast<const uint4*>(g_vth + go);                  \
            pvl[i] = *reinterpret_cast<const uint4*>(g_vtl + go);                  \
        }                                                                          \
    } while (0)

__global__ __launch_bounds__(256, 2) void pv_tc(float* __restrict__ attn)
{
    extern __shared__ char smem[];
    int tid = threadIdx.x;
    int z = blockIdx.y, q0 = blockIdx.x * 64;
    const uint32_t AH = 1024, AL = AH + 8192, VH = AL + 8192, VL = VH + 8192;

    float* s_lse = reinterpret_cast<float*>(smem);
    if (tid < 64) s_lse[tid] = g_lse[(size_t)z * LQ + q0 + tid];
    __syncthreads();

    uint32_t sb = smem_u32(smem);
    int w = tid >> 5, lane = tid & 31;
    int wy = w & 3, wx = w >> 2;
    float acc[4][4] = {};

    int arow = wy * 16 + (lane & 15);
    int arx = arow & 7;
    uint32_t aoffH = sb + AH + (uint32_t)arow * 128;
    uint32_t aoffL = sb + AL + (uint32_t)arow * 128;
    int ahib = lane >> 4;
    int nrow0 = wx * 32 + (lane & 7) + ((lane & 16) >> 1);
    int bhib = (lane >> 3) & 1;

    float* abase = attn + (size_t)z * LQ * LK + (size_t)q0 * LK;

    float4 pa[4];
    uint4 pvh[2], pvl[2];
    PV_LOAD_CHUNK(0);

    for (int kc = 0; kc < 32; ++kc) {
        int k0 = kc * 64;

        // convert prefetched attn: normalize, write final, hi/lo to smem
        #pragma unroll
        for (int i = 0; i < 4; ++i) {
            int idx = tid + i * 256;
            int row = idx >> 4, pos = idx & 15;
            float l = s_lse[row];
            float a0 = pa[i].x - l, a1 = pa[i].y - l, a2 = pa[i].z - l, a3 = pa[i].w - l;
            *reinterpret_cast<float4*>(abase + (size_t)row * LK + k0 + pos * 4) =
                make_float4(a0, a1, a2, a3);
            __nv_bfloat16 h0 = __float2bfloat16(a0), h1 = __float2bfloat16(a1);
            __nv_bfloat16 h2 = __float2bfloat16(a2), h3 = __float2bfloat16(a3);
            uint2 hv = make_uint2(pack2(h0, h1), pack2(h2, h3));
            uint2 lv = make_uint2(
                pack2(__float2bfloat16(a0 - __bfloat162float(h0)),
                      __float2bfloat16(a1 - __bfloat162float(h1))),
                pack2(__float2bfloat16(a2 - __bfloat162float(h2)),
                      __float2bfloat16(a3 - __bfloat162float(h3))));
            int ch = pos >> 1, half = pos & 1;
            uint32_t so = (uint32_t)row * 128 + (uint32_t)((ch ^ (row & 7)) << 4) + half * 8;
            *reinterpret_cast<uint2*>(smem + AH + so) = hv;
            *reinterpret_cast<uint2*>(smem + AL + so) = lv;
        }
        #pragma unroll
        for (int i = 0; i < 2; ++i) {
            int idx = tid + i * 256;
            int row = idx >> 3, ch = idx & 7;
            uint32_t so = (uint32_t)row * 128 + (uint32_t)((ch ^ (row & 7)) << 4);
            *reinterpret_cast<uint4*>(smem + VH + so) = pvh[i];
            *reinterpret_cast<uint4*>(smem + VL + so) = pvl[i];
        }
        __syncthreads();

        // prefetch next chunk — global latency overlaps the MMA below
        if (kc < 31) PV_LOAD_CHUNK(k0 + 64);

        #pragma unroll
        for (int s = 0; s < 4; ++s) {
            uint32_t ah[4], al[4];
            uint32_t ac = (uint32_t)(((s * 2 + ahib) ^ arx) << 4);
            LDSM_X4(ah[0], ah[1], ah[2], ah[3], aoffH + ac);
            LDSM_X4(al[0], al[1], al[2], al[3], aoffL + ac);
            #pragma unroll
            for (int g = 0; g < 2; ++g) {
                int r = nrow0 + g * 16;
                uint32_t bo = (uint32_t)r * 128 + (uint32_t)(((s * 2 + bhib) ^ (r & 7)) << 4);
                uint32_t bh[4], bl[4];
                LDSM_X4(bh[0], bh[1], bh[2], bh[3], sb + VH + bo);
                LDSM_X4(bl[0], bl[1], bl[2], bl[3], sb + VL + bo);
                #pragma unroll
                for (int t2 = 0; t2 < 2; ++t2) {
                    int nt = g * 2 + t2;
                    MMA_BF16(acc[nt], ah[0], ah[1], ah[2], ah[3], bh[t2 * 2], bh[t2 * 2 + 1]);
                    MMA_BF16(acc[nt], ah[0], ah[1], ah[2], ah[3], bl[t2 * 2], bl[t2 * 2 + 1]);
                    MMA_BF16(acc[nt], al[0], al[1], al[2], al[3], bh[t2 * 2], bh[t2 * 2 + 1]);
                }
            }
        }
        __syncthreads();
    }

    int b = z >> 1, h = z & 1;
    int r0 = q0 + wy * 16 + (lane >> 2);
    float* d0 = g_ho + ((size_t)b * LQ + r0) * HD + h * 64 + wx * 32 + (lane & 3) * 2;
    float* d1 = d0 + (size_t)8 * HD;
    #pragma unroll
    for (int nt = 0; nt < 4; ++nt) {
        *reinterpret_cast<float2*>(d0 + nt * 8) = make_float2(acc[nt][0], acc[nt][1]);
        *reinterpret_cast<float2*>(d1 + nt * 8) = make_float2(acc[nt][2], acc[nt][3]);
    }
}

// =====================================================================
extern "C" void kernel_launch(void* const* d_in, const int* in_sizes, int n_in,
                              void* d_out, int out_size)
{
    const float* Q    = (const float*)d_in[0];
    const float* K    = (const float*)d_in[1];
    const float* V    = (const float*)d_in[2];
    const int*   mask = (const int*)  d_in[3];
    const float* Wq   = (const float*)d_in[4];
    const float* bq   = (const float*)d_in[5];
    const float* Wk   = (const float*)d_in[6];
    const float* bk   = (const float*)d_in[7];
    const float* Wv   = (const float*)d_in[8];
    const float* bv   = (const float*)d_in[9];
    const float* Wo   = (const float*)d_in[10];
    const float* bo   = (const float*)d_in[11];

    float* out  = (float*)d_out;
    float* attn = out + (size_t)B_ * LQ * DM;

    __nv_bfloat16 *qh, *ql, *kh, *kl, *vth, *vtl;
    __nv_bfloat16 *wqh, *wql, *wkh, *wkl, *wvh, *wvl, *woh, *wol;
    float *gho;
    cudaGetSymbolAddress((void**)&qh,  g_qh);
    cudaGetSymbolAddress((void**)&ql,  g_ql);
    cudaGetSymbolAddress((void**)&kh,  g_kh);
    cudaGetSymbolAddress((void**)&kl,  g_kl);
    cudaGetSymbolAddress((void**)&vth, g_vth);
    cudaGetSymbolAddress((void**)&vtl, g_vtl);
    cudaGetSymbolAddress((void**)&gho, g_ho);
    cudaGetSymbolAddress((void**)&wqh, g_wqt_h);
    cudaGetSymbolAddress((void**)&wql, g_wqt_l);
    cudaGetSymbolAddress((void**)&wkh, g_wkt_h);
    cudaGetSymbolAddress((void**)&wkl, g_wkt_l);
    cudaGetSymbolAddress((void**)&wvh, g_wvt_h);
    cudaGetSymbolAddress((void**)&wvl, g_wvt_l);
    cudaGetSymbolAddress((void**)&woh, g_wot_h);
    cudaGetSymbolAddress((void**)&wol, g_wot_l);

    cudaFuncSetAttribute(qk_tc,    cudaFuncAttributeMaxDynamicSharedMemorySize, 66560);
    cudaFuncSetAttribute(pv_tc,    cudaFuncAttributeMaxDynamicSharedMemorySize, 33792);
    cudaFuncSetAttribute(mma_gemm, cudaFuncAttributeMaxDynamicSharedMemorySize, 49152);

    // weight prep: single launch for all 4 weights
    wprep_all<<<dim3(16, 16, 4), 256>>>(Wq, Wk, Wv, Wo);

    // projections (tensor)
    mma_gemm<<<dim3(1, (B_ * LQ) / 64), 256, 49152>>>(
        Q, DM, DM, wqh, wql, bq, 0, qh, ql, (float*)0, 0);
    mma_gemm<<<dim3(1, (B_ * LQ) / 64), 256, 49152>>>(
        K, DM, DM, wkh, wkl, bk, 0, kh, kl, (float*)0, 0);
    mma_gemm<<<dim3(1, (B_ * LQ) / 64), 256, 49152>>>(
        V, DM, DM, wvh, wvl, bv, 1, vth, vtl, (float*)0, 0);

    qk_tc<<<dim3(LK / 128, LQ / 128, B_ * NH), 256, 66560>>>(mask, attn);

    lse_reduce<<<(B_ * NH * LQ) / 256, 256>>>();

    pv_tc<<<dim3(LQ / 64, B_ * NH), 256, 33792>>>(attn);

    // out projection (tensor)
    mma_gemm<<<dim3(DM / 128, (B_ * LQ) / 64), 256, 49152>>>(
        gho, HD, HD, woh, wol, bo, 2, (__nv_bfloat16*)0, (__nv_bfloat16*)0, out, DM);
}

// round 17
// speedup vs baseline: 4.1804x; 1.2185x over previous
#include <cuda_runtime.h>
#include <cuda_bf16.h>
#include <math.h>
#include <stdint.h>

#define B_ 4
#define LQ 2048
#define LK 2048
#define DM 512
#define NH 2
#define DH 64
#define HD 128   /* NH*DH */

// ---------------- scratch (device globals; no allocation) ----------------
__device__ __nv_bfloat16 g_qh[(size_t)B_*NH*LQ*DH];
__device__ __nv_bfloat16 g_ql[(size_t)B_*NH*LQ*DH];
__device__ __nv_bfloat16 g_kh[(size_t)B_*NH*LK*DH];
__device__ __nv_bfloat16 g_kl[(size_t)B_*NH*LK*DH];
__device__ __nv_bfloat16 g_vth[(size_t)B_*NH*DH*LK];   // v transposed: [z][d][k]
__device__ __nv_bfloat16 g_vtl[(size_t)B_*NH*DH*LK];
__device__ float g_part[(size_t)B_*NH*LQ*32];
__device__ float g_lse [(size_t)B_*NH*LQ];
__device__ float g_ho  [(size_t)B_*LQ*HD];

// pre-transposed hi/lo weights: [n][k]
__device__ __nv_bfloat16 g_wqt_h[HD*DM], g_wqt_l[HD*DM];
__device__ __nv_bfloat16 g_wkt_h[HD*DM], g_wkt_l[HD*DM];
__device__ __nv_bfloat16 g_wvt_h[HD*DM], g_wvt_l[HD*DM];
__device__ __nv_bfloat16 g_wot_h[DM*HD], g_wot_l[DM*HD];

// ---------------- helpers ----------------
__device__ __forceinline__ uint32_t smem_u32(const void* p) {
    uint32_t a;
    asm("{ .reg .u64 t; cvta.to.shared.u64 t, %1; cvt.u32.u64 %0, t; }" : "=r"(a) : "l"(p));
    return a;
}
__device__ __forceinline__ uint32_t pack2(__nv_bfloat16 a, __nv_bfloat16 b) {
    __nv_bfloat162 t; t.x = a; t.y = b;
    return *reinterpret_cast<uint32_t*>(&t);
}

#define LDSM_X4(R0,R1,R2,R3,ADDR) \
    asm volatile("ldmatrix.sync.aligned.m8n8.x4.shared.b16 {%0,%1,%2,%3}, [%4];" \
        : "=r"(R0),"=r"(R1),"=r"(R2),"=r"(R3) : "r"(ADDR))

#define MMA_BF16(C,A0,A1,A2,A3,B0,B1) \
    asm volatile("mma.sync.aligned.m16n8k16.row.col.f32.bf16.bf16.f32 " \
        "{%0,%1,%2,%3}, {%4,%5,%6,%7}, {%8,%9}, {%0,%1,%2,%3};" \
        : "+f"((C)[0]),"+f"((C)[1]),"+f"((C)[2]),"+f"((C)[3]) \
        : "r"(A0),"r"(A1),"r"(A2),"r"(A3),"r"(B0),"r"(B1))

#define CP_ASYNC16(DST, SRC) \
    asm volatile("cp.async.cg.shared.global [%0], [%1], 16;" :: "r"(DST), "l"(SRC))
#define CP_COMMIT() asm volatile("cp.async.commit_group;" ::: "memory")
#define CP_WAIT1()  asm volatile("cp.async.wait_group 1;" ::: "memory")
#define CP_WAIT0()  asm volatile("cp.async.wait_group 0;" ::: "memory")

__device__ __forceinline__ float tanh10(float x) {
    x = fminf(fmaxf(x, -15.0f), 15.0f);
    float e = __expf(2.0f * x);
    return 10.0f * __fdividef(e - 1.0f, e + 1.0f);
}

// =====================================================================
// Weight prep (all 4 weights in ONE launch)
// =====================================================================
__global__ __launch_bounds__(256) void wprep_all(
    const float* __restrict__ Wq, const float* __restrict__ Wk,
    const float* __restrict__ Wv, const float* __restrict__ Wo)
{
    __shared__ float ts[32][33];
    int z = blockIdx.z;
    const float* W;
    __nv_bfloat16 *th, *tl;
    int K, N;
    if (z == 0)      { W = Wq; th = g_wqt_h; tl = g_wqt_l; K = DM; N = HD; }
    else if (z == 1) { W = Wk; th = g_wkt_h; tl = g_wkt_l; K = DM; N = HD; }
    else if (z == 2) { W = Wv; th = g_wvt_h; tl = g_wvt_l; K = DM; N = HD; }
    else             { W = Wo; th = g_wot_h; tl = g_wot_l; K = HD; N = DM; }

    int n0 = blockIdx.x * 32, k0 = blockIdx.y * 32;
    if (n0 >= N || k0 >= K) return;

    int tx = threadIdx.x & 31, ty = threadIdx.x >> 5;
    #pragma unroll
    for (int i = 0; i < 4; ++i) {
        int k = ty + i * 8;
        ts[k][tx] = W[(size_t)(k0 + k) * N + n0 + tx];
    }
    __syncthreads();
    #pragma unroll
    for (int i = 0; i < 4; ++i) {
        int n = ty + i * 8;
        float v = ts[tx][n];
        __nv_bfloat16 h = __float2bfloat16(v);
        th[(size_t)(n0 + n) * K + k0 + tx] = h;
        tl[(size_t)(n0 + n) * K + k0 + tx] = __float2bfloat16(v - __bfloat162float(h));
    }
}

// =====================================================================
// Pipelined tensor-core GEMM core: C[64 x 128] per block.
// A fp32 (register-prefetched, converted hi/lo), B weights via cp.async
// double-buffered smem ring. modes: 0 q/k hi/lo, 1 v transposed, 2 fp32.
// smem: ASH 8K | ASL 8K | B ring: {BSH,BSL} x2 = 64K. total 80K.
// =====================================================================
__device__ __forceinline__ void mma_gemm_core(
    const float* __restrict__ A, int lda, int K,
    const __nv_bfloat16* __restrict__ WtH, const __nv_bfloat16* __restrict__ WtL,
    const float* __restrict__ bias, int mode,
    __nv_bfloat16* __restrict__ oh, __nv_bfloat16* __restrict__ ol,
    float* __restrict__ Cout, int ldc,
    char* smem, int row0, int col0)
{
    const uint32_t ASH = 0, ASL = 8192;
    const uint32_t BBUF[2] = {16384, 49152};      // each: BSH at +0, BSL at +16384
    int tid = threadIdx.x;

    uint32_t sb = smem_u32(smem);
    int w = tid >> 5, lane = tid & 31;
    int wy = w & 3, wx = w >> 2;

    float acc[8][4] = {};

    int arow = wy * 16 + (lane & 15);
    int arx = arow & 7;
    uint32_t aoffH = sb + ASH + (uint32_t)arow * 128;
    uint32_t aoffL = sb + ASL + (uint32_t)arow * 128;
    int ahib = lane >> 4;
    int nrow0 = wx * 64 + (lane & 7) + ((lane & 16) >> 1);
    int bhib = (lane >> 3) & 1;

    // B staging coords (per thread, 4 x 16B per hi/lo tile per chunk)
    int bn[4], bch[4];
    uint32_t bso[4];
    #pragma unroll
    for (int i = 0; i < 4; ++i) {
        int e = tid + i * 256;
        bn[i] = e >> 3; bch[i] = e & 7;
        bso[i] = (uint32_t)bn[i] * 128 + (uint32_t)((bch[i] ^ (bn[i] & 7)) << 4);
    }
    // A staging coords
    int ar[4], ak[4];
    uint32_t aso[4];
    #pragma unroll
    for (int i = 0; i < 4; ++i) {
        int e = tid + i * 256;
        ar[i] = e >> 4; ak[i] = (e & 15) * 4;
        aso[i] = (uint32_t)ar[i] * 128 + (uint32_t)(((ak[i] >> 3) ^ (ar[i] & 7)) << 4)
               + (uint32_t)((ak[i] & 7) * 2);
    }

    int nchunks = K >> 6;

    // prologue: B chunk0 via cp.async, A chunk0 into regs
    #pragma unroll
    for (int i = 0; i < 4; ++i) {
        size_t go = (size_t)(col0 + bn[i]) * K + bch[i] * 8;
        CP_ASYNC16(sb + BBUF[0] + bso[i],         WtH + go);
        CP_ASYNC16(sb + BBUF[0] + 16384 + bso[i], WtL + go);
    }
    CP_COMMIT();
    float4 pa[4];
    #pragma unroll
    for (int i = 0; i < 4; ++i)
        pa[i] = *reinterpret_cast<const float4*>(&A[(size_t)(row0 + ar[i]) * lda + ak[i]]);

    for (int kc = 0; kc < nchunks; ++kc) {
        uint32_t bb = BBUF[kc & 1];

        // convert prefetched A -> hi/lo smem
        #pragma unroll
        for (int i = 0; i < 4; ++i) {
            __nv_bfloat16 h0 = __float2bfloat16(pa[i].x), h1 = __float2bfloat16(pa[i].y);
            __nv_bfloat16 h2 = __float2bfloat16(pa[i].z), h3 = __float2bfloat16(pa[i].w);
            *reinterpret_cast<uint2*>(smem + ASH + aso[i]) =
                make_uint2(pack2(h0, h1), pack2(h2, h3));
            *reinterpret_cast<uint2*>(smem + ASL + aso[i]) = make_uint2(
                pack2(__float2bfloat16(pa[i].x - __bfloat162float(h0)),
                      __float2bfloat16(pa[i].y - __bfloat162float(h1))),
                pack2(__float2bfloat16(pa[i].z - __bfloat162float(h2)),
                      __float2bfloat16(pa[i].w - __bfloat162float(h3))));
        }

        if (kc + 1 < nchunks) {
            uint32_t nb = BBUF[(kc + 1) & 1];
            #pragma unroll
            for (int i = 0; i < 4; ++i) {
                size_t go = (size_t)(col0 + bn[i]) * K + (kc + 1) * 64 + bch[i] * 8;
                CP_ASYNC16(sb + nb + bso[i],         WtH + go);
                CP_ASYNC16(sb + nb + 16384 + bso[i], WtL + go);
            }
            CP_COMMIT();
            // prefetch next A (after pa consumed above)
            #pragma unroll
            for (int i = 0; i < 4; ++i)
                pa[i] = *reinterpret_cast<const float4*>(
                    &A[(size_t)(row0 + ar[i]) * lda + (kc + 1) * 64 + ak[i]]);
            CP_WAIT1();
        } else {
            CP_WAIT0();
        }
        __syncthreads();

        #pragma unroll
        for (int s = 0; s < 4; ++s) {
            uint32_t ah[4], al[4];
            uint32_t ac = (uint32_t)(((s * 2 + ahib) ^ arx) << 4);
            LDSM_X4(ah[0], ah[1], ah[2], ah[3], aoffH + ac);
            LDSM_X4(al[0], al[1], al[2], al[3], aoffL + ac);
            #pragma unroll
            for (int g = 0; g < 4; ++g) {
                int r = nrow0 + g * 16;
                uint32_t bo = (uint32_t)r * 128 + (uint32_t)(((s * 2 + bhib) ^ (r & 7)) << 4);
                uint32_t bh[4], bl[4];
                LDSM_X4(bh[0], bh[1], bh[2], bh[3], sb + bb + bo);
                LDSM_X4(bl[0], bl[1], bl[2], bl[3], sb + bb + 16384 + bo);
                #pragma unroll
                for (int t2 = 0; t2 < 2; ++t2) {
                    int nt = g * 2 + t2;
                    MMA_BF16(acc[nt], ah[0], ah[1], ah[2], ah[3], bh[t2 * 2], bh[t2 * 2 + 1]);
                    MMA_BF16(acc[nt], ah[0], ah[1], ah[2], ah[3], bl[t2 * 2], bl[t2 * 2 + 1]);
                    MMA_BF16(acc[nt], al[0], al[1], al[2], al[3], bh[t2 * 2], bh[t2 * 2 + 1]);
                }
            }
        }
        __syncthreads();
    }

    if (mode == 2) {
        int r = row0 + wy * 16 + (lane >> 2);
        #pragma unroll
        for (int nt = 0; nt < 8; ++nt) {
            int c = col0 + wx * 64 + nt * 8 + (lane & 3) * 2;
            float b0 = bias[c], b1 = bias[c + 1];
            *reinterpret_cast<float2*>(&Cout[(size_t)r * ldc + c]) =
                make_float2(acc[nt][0] + b0, acc[nt][1] + b1);
            *reinterpret_cast<float2*>(&Cout[(size_t)(r + 8) * ldc + c]) =
                make_float2(acc[nt][2] + b0, acc[nt][3] + b1);
        }
    } else if (mode == 0) {
        #pragma unroll
        for (int nt = 0; nt < 8; ++nt) {
            int cl = wx * 64 + nt * 8 + (lane & 3) * 2;
            float b0 = bias[cl], b1 = bias[cl + 1];
            int hh = cl >> 6, cc = cl & 63;
            #pragma unroll
            for (int hf = 0; hf < 2; ++hf) {
                int rg = row0 + wy * 16 + hf * 8 + (lane >> 2);
                int b = rg >> 11, r = rg & 2047;
                size_t off = ((size_t)(b * NH + hh) * LQ + r) * 64 + cc;
                float v0 = acc[nt][hf * 2 + 0] + b0;
                float v1 = acc[nt][hf * 2 + 1] + b1;
                __nv_bfloat16 h0 = __float2bfloat16(v0), h1 = __float2bfloat16(v1);
                *reinterpret_cast<uint32_t*>(&oh[off]) = pack2(h0, h1);
                *reinterpret_cast<uint32_t*>(&ol[off]) =
                    pack2(__float2bfloat16(v0 - __bfloat162float(h0)),
                          __float2bfloat16(v1 - __bfloat162float(h1)));
            }
        }
    } else {
        float* ts = reinterpret_cast<float*>(smem);   // [64][132] overlays ring
        #pragma unroll
        for (int nt = 0; nt < 8; ++nt) {
            int cl = wx * 64 + nt * 8 + (lane & 3) * 2;
            float b0 = bias[cl], b1 = bias[cl + 1];
            int r = wy * 16 + (lane >> 2);
            ts[r * 132 + cl]           = acc[nt][0] + b0;
            ts[r * 132 + cl + 1]       = acc[nt][1] + b1;
            ts[(r + 8) * 132 + cl]     = acc[nt][2] + b0;
            ts[(r + 8) * 132 + cl + 1] = acc[nt][3] + b1;
        }
        __syncthreads();

        int h2 = tid >> 7, d = (tid >> 1) & 63, seg = tid & 1;
        int b = row0 >> 11;
        int kbase = (row0 & 2047) + seg * 32;
        size_t off = ((size_t)(b * NH + h2) * 64 + d) * (size_t)LK + kbase;
        int c = h2 * 64 + d;
        uint32_t hw[16], lw[16];
        #pragma unroll
        for (int p = 0; p < 16; ++p) {
            float v0 = ts[(seg * 32 + p * 2 + 0) * 132 + c];
            float v1 = ts[(seg * 32 + p * 2 + 1) * 132 + c];
            __nv_bfloat16 h0 = __float2bfloat16(v0), h1 = __float2bfloat16(v1);
            hw[p] = pack2(h0, h1);
            lw[p] = pack2(__float2bfloat16(v0 - __bfloat162float(h0)),
                          __float2bfloat16(v1 - __bfloat162float(h1)));
        }
        #pragma unroll
        for (int u = 0; u < 4; ++u) {
            *reinterpret_cast<uint4*>(&g_vth[off + u * 8]) =
                make_uint4(hw[u * 4], hw[u * 4 + 1], hw[u * 4 + 2], hw[u * 4 + 3]);
            *reinterpret_cast<uint4*>(&g_vtl[off + u * 8]) =
                make_uint4(lw[u * 4], lw[u * 4 + 1], lw[u * 4 + 2], lw[u * 4 + 3]);
        }
    }
}

// fused Q/K/V projection: z selects input/weights/mode
__global__ __launch_bounds__(256) void proj_fused(
    const float* __restrict__ Q, const float* __restrict__ K,
    const float* __restrict__ V,
    const float* __restrict__ bq, const float* __restrict__ bk,
    const float* __restrict__ bv)
{
    extern __shared__ char smem[];
    int z = blockIdx.z;
    const float* A;
    const __nv_bfloat16 *WtH, *WtL;
    const float* bias;
    __nv_bfloat16 *oh, *ol;
    int mode;
    if (z == 0)      { A = Q; WtH = g_wqt_h; WtL = g_wqt_l; bias = bq; oh = g_qh; ol = g_ql; mode = 0; }
    else if (z == 1) { A = K; WtH = g_wkt_h; WtL = g_wkt_l; bias = bk; oh = g_kh; ol = g_kl; mode = 0; }
    else             { A = V; WtH = g_wvt_h; WtL = g_wvt_l; bias = bv; oh = g_vth; ol = g_vtl; mode = 1; }
    mma_gemm_core(A, DM, DM, WtH, WtL, bias, mode, oh, ol, (float*)0, 0,
                  smem, blockIdx.y * 64, 0);
}

// out projection
__global__ __launch_bounds__(256) void outproj(
    const float* __restrict__ bo, float* __restrict__ out)
{
    extern __shared__ char smem[];
    mma_gemm_core(g_ho, HD, HD, g_wot_h, g_wot_l, bo, 2,
                  (__nv_bfloat16*)0, (__nv_bfloat16*)0, out, DM,
                  smem, blockIdx.y * 64, blockIdx.x * 128);
}

// =====================================================================
// QK scores via mma.sync (unchanged from R13)
// =====================================================================
__global__ __launch_bounds__(256, 2) void qk_tc(const int* __restrict__ mask,
                                                float* __restrict__ attn)
{
    extern __shared__ char smem[];
    int tid = threadIdx.x;
    int z = blockIdx.z;
    int q0 = blockIdx.y * 128, k0 = blockIdx.x * 128;
    const uint32_t QH = 1024, QL = QH + 16384, KH = QL + 16384, KL = KH + 16384;

    int* smask = reinterpret_cast<int*>(smem);
    if (tid < 128) smask[tid] = mask[(z >> 1) * LK + k0 + tid];

    {
        size_t qrow = (size_t)z * LQ + q0;
        size_t krow = (size_t)z * LK + k0;
        #pragma unroll
        for (int i = 0; i < 4; ++i) {
            int idx = tid + i * 256;
            int row = idx >> 3, ch = idx & 7;
            uint32_t so = (uint32_t)row * 128 + (uint32_t)((ch ^ (row & 7)) << 4);
            size_t go = (qrow + row) * 64 + ch * 8;
            size_t gk = (krow + row) * 64 + ch * 8;
            *reinterpret_cast<uint4*>(smem + QH + so) = *reinterpret_cast<const uint4*>(g_qh + go);
            *reinterpret_cast<uint4*>(smem + QL + so) = *reinterpret_cast<const uint4*>(g_ql + go);
            *reinterpret_cast<uint4*>(smem + KH + so) = *reinterpret_cast<const uint4*>(g_kh + gk);
            *reinterpret_cast<uint4*>(smem + KL + so) = *reinterpret_cast<const uint4*>(g_kl + gk);
        }
    }
    __syncthreads();

    uint32_t sb = smem_u32(smem);
    int w = tid >> 5, lane = tid & 31;
    int wy = w & 3, wx = w >> 2;

    float acc[2][8][4] = {};

    uint32_t aoffH[2], aoffL[2];
    int arx[2];
    #pragma unroll
    for (int mt = 0; mt < 2; ++mt) {
        int r = wy * 32 + mt * 16 + (lane & 15);
        arx[mt] = r & 7;
        aoffH[mt] = sb + QH + (uint32_t)r * 128;
        aoffL[mt] = sb + QL + (uint32_t)r * 128;
    }
    int ahib = lane >> 4;
    int nrow0 = wx * 64 + (lane & 7) + ((lane & 16) >> 1);
    int bhib = (lane >> 3) & 1;

    #pragma unroll
    for (int s = 0; s < 4; ++s) {
        uint32_t ah[2][4], al[2][4];
        #pragma unroll
        for (int mt = 0; mt < 2; ++mt) {
            uint32_t c = (uint32_t)(((s * 2 + ahib) ^ arx[mt]) << 4);
            LDSM_X4(ah[mt][0], ah[mt][1], ah[mt][2], ah[mt][3], aoffH[mt] + c);
            LDSM_X4(al[mt][0], al[mt][1], al[mt][2], al[mt][3], aoffL[mt] + c);
        }
        #pragma unroll
        for (int g = 0; g < 4; ++g) {
            int r = nrow0 + g * 16;
            uint32_t bo = (uint32_t)r * 128 + (uint32_t)(((s * 2 + bhib) ^ (r & 7)) << 4);
            uint32_t bh[4], bl[4];
            LDSM_X4(bh[0], bh[1], bh[2], bh[3], sb + KH + bo);
            LDSM_X4(bl[0], bl[1], bl[2], bl[3], sb + KL + bo);
            #pragma unroll
            for (int t2 = 0; t2 < 2; ++t2) {
                int nt = g * 2 + t2;
                #pragma unroll
                for (int mt = 0; mt < 2; ++mt) {
                    MMA_BF16(acc[mt][nt], ah[mt][0], ah[mt][1], ah[mt][2], ah[mt][3],
                             bh[t2 * 2], bh[t2 * 2 + 1]);
                    MMA_BF16(acc[mt][nt], ah[mt][0], ah[mt][1], ah[mt][2], ah[mt][3],
                             bl[t2 * 2], bl[t2 * 2 + 1]);
                    MMA_BF16(acc[mt][nt], al[mt][0], al[mt][1], al[mt][2], al[mt][3],
                             bh[t2 * 2], bh[t2 * 2 + 1]);
                }
            }
        }
    }

    float rs[2][2] = {};
    #pragma unroll
    for (int mt = 0; mt < 2; ++mt) {
        int r = q0 + wy * 32 + mt * 16 + (lane >> 2);
        float* row0p = attn + (size_t)z * LQ * LK + (size_t)r * LK + k0;
        float* row1p = row0p + (size_t)8 * LK;
        #pragma unroll
        for (int nt = 0; nt < 8; ++nt) {
            int cl = wx * 64 + nt * 8 + (lane & 3) * 2;
            int m0 = smask[cl], m1 = smask[cl + 1];
            float s0 = tanh10(acc[mt][nt][0] * 0.125f);
            float s1 = tanh10(acc[mt][nt][1] * 0.125f);
            float s2 = tanh10(acc[mt][nt][2] * 0.125f);
            float s3 = tanh10(acc[mt][nt][3] * 0.125f);
            if (m0) { s0 = -10.0f; s2 = -10.0f; }
            if (m1) { s1 = -10.0f; s3 = -10.0f; }
            *reinterpret_cast<float2*>(row0p + cl) = make_float2(s0, s1);
            *reinterpret_cast<float2*>(row1p + cl) = make_float2(s2, s3);
            rs[mt][0] += __expf(s0) + __expf(s1);
            rs[mt][1] += __expf(s2) + __expf(s3);
        }
    }
    #pragma unroll
    for (int mt = 0; mt < 2; ++mt)
        #pragma unroll
        for (int hf = 0; hf < 2; ++hf) {
            float v = rs[mt][hf];
            v += __shfl_xor_sync(0xffffffffu, v, 1);
            v += __shfl_xor_sync(0xffffffffu, v, 2);
            rs[mt][hf] = v;
        }
    if ((lane & 3) == 0) {
        int col = blockIdx.x * 2 + wx;
        #pragma unroll
        for (int mt = 0; mt < 2; ++mt)
            #pragma unroll
            for (int hf = 0; hf < 2; ++hf) {
                int r = q0 + wy * 32 + mt * 16 + hf * 8 + (lane >> 2);
                g_part[((size_t)z * LQ + r) * 32 + col] = rs[mt][hf];
            }
    }
}

// =====================================================================
__global__ __launch_bounds__(256) void lse_reduce()
{
    int r = blockIdx.x * 256 + threadIdx.x;
    float s = 0.0f;
    #pragma unroll
    for (int j = 0; j < 32; ++j) s += g_part[(size_t)r * 32 + j];
    g_lse[r] = logf(s);
}

// =====================================================================
// PV via mma.sync — register-prefetch pipeline + 2 blocks/SM (R13)
// =====================================================================
#define PV_LOAD_CHUNK(K0)                                                          \
    do {                                                                           \
        _Pragma("unroll")                                                          \
        for (int i = 0; i < 4; ++i) {                                              \
            int idx = tid + i * 256;                                               \
            int row = idx >> 4, pos = idx & 15;                                    \
            pa[i] = *reinterpret_cast<const float4*>(                              \
                abase + (size_t)row * LK + (K0) + pos * 4);                        \
        }                                                                          \
        _Pragma("unroll")                                                          \
        for (int i = 0; i < 2; ++i) {                                              \
            int idx = tid + i * 256;                                               \
            int row = idx >> 3, ch = idx & 7;                                      \
            size_t go = ((size_t)z * 64 + row) * (size_t)LK + (K0) + ch * 8;       \
            pvh[i] = *reinterpret_cast<const uint4*>(g_vth + go);                  \
            pvl[i] = *reinterpret_cast<const uint4*>(g_vtl + go);                  \
        }                                                                          \
    } while (0)

__global__ __launch_bounds__(256, 2) void pv_tc(float* __restrict__ attn)
{
    extern __shared__ char smem[];
    int tid = threadIdx.x;
    int z = blockIdx.y, q0 = blockIdx.x * 64;
    const uint32_t AH = 1024, AL = AH + 8192, VH = AL + 8192, VL = VH + 8192;

    float* s_lse = reinterpret_cast<float*>(smem);
    if (tid < 64) s_lse[tid] = g_lse[(size_t)z * LQ + q0 + tid];
    __syncthreads();

    uint32_t sb = smem_u32(smem);
    int w = tid >> 5, lane = tid & 31;
    int wy = w & 3, wx = w >> 2;
    float acc[4][4] = {};

    int arow = wy * 16 + (lane & 15);
    int arx = arow & 7;
    uint32_t aoffH = sb + AH + (uint32_t)arow * 128;
    uint32_t aoffL = sb + AL + (uint32_t)arow * 128;
    int ahib = lane >> 4;
    int nrow0 = wx * 32 + (lane & 7) + ((lane & 16) >> 1);
    int bhib = (lane >> 3) & 1;

    float* abase = attn + (size_t)z * LQ * LK + (size_t)q0 * LK;

    float4 pa[4];
    uint4 pvh[2], pvl[2];
    PV_LOAD_CHUNK(0);

    for (int kc = 0; kc < 32; ++kc) {
        int k0 = kc * 64;

        #pragma unroll
        for (int i = 0; i < 4; ++i) {
            int idx = tid + i * 256;
            int row = idx >> 4, pos = idx & 15;
            float l = s_lse[row];
            float a0 = pa[i].x - l, a1 = pa[i].y - l, a2 = pa[i].z - l, a3 = pa[i].w - l;
            *reinterpret_cast<float4*>(abase + (size_t)row * LK + k0 + pos * 4) =
                make_float4(a0, a1, a2, a3);
            __nv_bfloat16 h0 = __float2bfloat16(a0), h1 = __float2bfloat16(a1);
            __nv_bfloat16 h2 = __float2bfloat16(a2), h3 = __float2bfloat16(a3);
            uint2 hv = make_uint2(pack2(h0, h1), pack2(h2, h3));
            uint2 lv = make_uint2(
                pack2(__float2bfloat16(a0 - __bfloat162float(h0)),
                      __float2bfloat16(a1 - __bfloat162float(h1))),
                pack2(__float2bfloat16(a2 - __bfloat162float(h2)),
                      __float2bfloat16(a3 - __bfloat162float(h3))));
            int ch = pos >> 1, half = pos & 1;
            uint32_t so = (uint32_t)row * 128 + (uint32_t)((ch ^ (row & 7)) << 4) + half * 8;
            *reinterpret_cast<uint2*>(smem + AH + so) = hv;
            *reinterpret_cast<uint2*>(smem + AL + so) = lv;
        }
        #pragma unroll
        for (int i = 0; i < 2; ++i) {
            int idx = tid + i * 256;
            int row = idx >> 3, ch = idx & 7;
            uint32_t so = (uint32_t)row * 128 + (uint32_t)((ch ^ (row & 7)) << 4);
            *reinterpret_cast<uint4*>(smem + VH + so) = pvh[i];
            *reinterpret_cast<uint4*>(smem + VL + so) = pvl[i];
        }
        __syncthreads();

        if (kc < 31) PV_LOAD_CHUNK(k0 + 64);

        #pragma unroll
        for (int s = 0; s < 4; ++s) {
            uint32_t ah[4], al[4];
            uint32_t ac = (uint32_t)(((s * 2 + ahib) ^ arx) << 4);
            LDSM_X4(ah[0], ah[1], ah[2], ah[3], aoffH + ac);
            LDSM_X4(al[0], al[1], al[2], al[3], aoffL + ac);
            #pragma unroll
            for (int g = 0; g < 2; ++g) {
                int r = nrow0 + g * 16;
                uint32_t bo = (uint32_t)r * 128 + (uint32_t)(((s * 2 + bhib) ^ (r & 7)) << 4);
                uint32_t bh[4], bl[4];
                LDSM_X4(bh[0], bh[1], bh[2], bh[3], sb + VH + bo);
                LDSM_X4(bl[0], bl[1], bl[2], bl[3], sb + VL + bo);
                #pragma unroll
                for (int t2 = 0; t2 < 2; ++t2) {
                    int nt = g * 2 + t2;
                    MMA_BF16(acc[nt], ah[0], ah[1], ah[2], ah[3], bh[t2 * 2], bh[t2 * 2 + 1]);
                    MMA_BF16(acc[nt], ah[0], ah[1], ah[2], ah[3], bl[t2 * 2], bl[t2 * 2 + 1]);
                    MMA_BF16(acc[nt], al[0], al[1], al[2], al[3], bh[t2 * 2], bh[t2 * 2 + 1]);
                }
            }
        }
        __syncthreads();
    }

    int b = z >> 1, h = z & 1;
    int r0 = q0 + wy * 16 + (lane >> 2);
    float* d0 = g_ho + ((size_t)b * LQ + r0) * HD + h * 64 + wx * 32 + (lane & 3) * 2;
    float* d1 = d0 + (size_t)8 * HD;
    #pragma unroll
    for (int nt = 0; nt < 4; ++nt) {
        *reinterpret_cast<float2*>(d0 + nt * 8) = make_float2(acc[nt][0], acc[nt][1]);
        *reinterpret_cast<float2*>(d1 + nt * 8) = make_float2(acc[nt][2], acc[nt][3]);
    }
}

// =====================================================================
extern "C" void kernel_launch(void* const* d_in, const int* in_sizes, int n_in,
                              void* d_out, int out_size)
{
    const float* Q    = (const float*)d_in[0];
    const float* K    = (const float*)d_in[1];
    const float* V    = (const float*)d_in[2];
    const int*   mask = (const int*)  d_in[3];
    const float* Wq   = (const float*)d_in[4];
    const float* bq   = (const float*)d_in[5];
    const float* Wk   = (const float*)d_in[6];
    const float* bk   = (const float*)d_in[7];
    const float* Wv   = (const float*)d_in[8];
    const float* bv   = (const float*)d_in[9];
    const float* Wo   = (const float*)d_in[10];
    const float* bo   = (const float*)d_in[11];

    float* out  = (float*)d_out;
    float* attn = out + (size_t)B_ * LQ * DM;

    cudaFuncSetAttribute(qk_tc,      cudaFuncAttributeMaxDynamicSharedMemorySize, 66560);
    cudaFuncSetAttribute(pv_tc,      cudaFuncAttributeMaxDynamicSharedMemorySize, 33792);
    cudaFuncSetAttribute(proj_fused, cudaFuncAttributeMaxDynamicSharedMemorySize, 81920);
    cudaFuncSetAttribute(outproj,    cudaFuncAttributeMaxDynamicSharedMemorySize, 81920);

    wprep_all<<<dim3(16, 16, 4), 256>>>(Wq, Wk, Wv, Wo);

    proj_fused<<<dim3(1, (B_ * LQ) / 64, 3), 256, 81920>>>(Q, K, V, bq, bk, bv);

    qk_tc<<<dim3(LK / 128, LQ / 128, B_ * NH), 256, 66560>>>(mask, attn);

    lse_reduce<<<(B_ * NH * LQ) / 256, 256>>>();

    pv_tc<<<dim3(LQ / 64, B_ * NH), 256, 33792>>>(attn);

    outproj<<<dim3(DM / 128, (B_ * LQ) / 64), 256, 81920>>>(bo, out);
}